// round 13
// baseline (speedup 1.0000x reference)
#include <cuda_runtime.h>
#include <cstdint>

#define B_ 8
#define C_ 384
#define L_ 1024
#define H_ 6
#define D_ 64
#define NW_ 9   // 2*window+1

// Scratch (allocation-free rule: device globals).
__device__ float g_qT[B_*L_*C_];    // [b][l][c] tf32
__device__ float g_kT[B_*L_*C_];    // [b][l][c] tf32
__device__ float g_vCL[B_*C_*L_];   // [b][c][l] tf32  (V kept channel-major)
__device__ float g_xT[B_*L_*C_];    // [b][l][c] tf32
__device__ float g_resT[B_*L_*C_];  // [b][l][c] tf32
__device__ float g_wr[4*C_*C_];     // tf32 wq,wk,wv,wo

__device__ __forceinline__ uint32_t f2tf32(float f) {
    uint32_t r;
    asm("cvt.rna.tf32.f32 %0, %1;" : "=r"(r) : "f"(f));
    return r;
}

__device__ __forceinline__ void mma_tf32(float* d, const uint32_t* a,
                                         uint32_t b0, uint32_t b1) {
    asm volatile("mma.sync.aligned.m16n8k8.row.col.f32.tf32.tf32.f32 "
                 "{%0,%1,%2,%3}, {%4,%5,%6,%7}, {%8,%9}, {%0,%1,%2,%3};"
                 : "+f"(d[0]), "+f"(d[1]), "+f"(d[2]), "+f"(d[3])
                 : "r"(a[0]), "r"(a[1]), "r"(a[2]), "r"(a[3]),
                   "r"(b0), "r"(b1));
}

// 4-matrix ldmatrix: reg i <- 8x(16B) tile i; lane l gets (row l>>2, word l&3).
__device__ __forceinline__ void ldsm4(uint32_t d[4], uint32_t addr) {
    asm volatile("ldmatrix.sync.aligned.m8n8.x4.shared.b16 {%0,%1,%2,%3}, [%4];"
                 : "=r"(d[0]), "=r"(d[1]), "=r"(d[2]), "=r"(d[3]) : "r"(addr));
}

__device__ __forceinline__ uint32_t smem_u32(const void* p) {
    uint32_t a;
    asm("{ .reg .u64 t; cvta.to.shared.u64 t, %1; cvt.u32.u64 %0, t; }"
        : "=r"(a) : "l"(p));
    return a;
}
__device__ __forceinline__ void cp_async16(uint32_t s, const void* g) {
    asm volatile("cp.async.cg.shared.global [%0], [%1], 16;" :: "r"(s), "l"(g));
}
#define CP_COMMIT() asm volatile("cp.async.commit_group;" ::: "memory")
#define CP_WAIT1()  asm volatile("cp.async.wait_group 1;" ::: "memory")
#define CP_WAIT0()  asm volatile("cp.async.wait_group 0;" ::: "memory")

// ===========================================================================
// Transpose + tf32 round: dst[b][col][row] = rna_tf32(src[b][row][col]).
// ===========================================================================
__global__ __launch_bounds__(256) void transpose_kernel(const float* __restrict__ src,
                                                        float* __restrict__ dst,
                                                        int rows, int cols) {
    __shared__ float tile[32][33];
    const int b = blockIdx.z;
    const int r0 = blockIdx.y * 32;
    const int c0 = blockIdx.x * 32;
    const int tx = threadIdx.x & 31, ty = threadIdx.x >> 5;
    const float* sb = src + (size_t)b * rows * cols;
    float* db = dst + (size_t)b * rows * cols;
#pragma unroll
    for (int i = 0; i < 4; i++)
        tile[ty + i * 8][tx] = sb[(size_t)(r0 + ty + i * 8) * cols + c0 + tx];
    __syncthreads();
#pragma unroll
    for (int i = 0; i < 4; i++)
        db[(size_t)(c0 + ty + i * 8) * rows + r0 + tx] =
            __uint_as_float(f2tf32(tile[tx][ty + i * 8]));
}

// ===========================================================================
// Round the four weight matrices to tf32 once.
// ===========================================================================
__global__ __launch_bounds__(256) void round_w(const float* __restrict__ w0,
                                               const float* __restrict__ w1,
                                               const float* __restrict__ w2,
                                               const float* __restrict__ w3,
                                               float* __restrict__ dst) {
    const int m = blockIdx.y;
    const float* src = (m == 0) ? w0 : (m == 1) ? w1 : (m == 2) ? w2 : w3;
    int idx = (blockIdx.x * 256 + threadIdx.x) * 4;
    float4 v = *(const float4*)(src + idx);
    uint4 t = make_uint4(f2tf32(v.x), f2tf32(v.y), f2tf32(v.z), f2tf32(v.w));
    *(uint4*)(dst + (size_t)m * C_ * C_ + idx) = t;
}

// ===========================================================================
// cp.async double-buffered tf32 GEMM core, ldmatrix fragment loads.
// Tile 128x128, K chunks of 32. Smem: 4 buffers of [128][36].
// ===========================================================================
#define GEMM_SMEMF (4 * 128 * 36)   // 73728 bytes

__device__ __forceinline__ void gemm_stage(uint32_t sa, uint32_t sb,
                                           const float* Ag, const float* Bg,
                                           int c0, int tid) {
    const int r_ = tid >> 3;
    const int u  = (tid & 7) * 4;
#pragma unroll
    for (int it = 0; it < 4; it++) {
        int row = it * 32 + r_;
        uint32_t so = (uint32_t)(row * 36 + u) * 4;
        cp_async16(sa + so, Ag + (size_t)row * C_ + c0 + u);
        cp_async16(sb + so, Bg + (size_t)row * C_ + c0 + u);
    }
}

__device__ __forceinline__ void gemm_core(float acc[2][8][4], float* smem,
                                          const float* Ag, const float* Bg,
                                          int tid) {
    const int lane = tid & 31;
    const int wid = tid >> 5;
    const int warpM = wid & 3, warpN = wid >> 2;
    const int tile = lane >> 3, tr = lane & 7;
    // A-frag lane address: tiles {a0,a1,a2,a3} = rows(+0,+8,+0,+8), k(+0,+0,+4,+4)
    const int arow = ((tile & 1) ? 8 : 0) + tr;
    const int akof = (tile & 2) ? 4 : 0;
    // B-frag lane address: tiles {b0,b1,b0',b1'} = rows(+0,+0,+8,+8), k(+0,+4,+0,+4)
    const int brow = ((tile & 2) ? 8 : 0) + tr;
    const int bkof = (tile & 1) ? 4 : 0;

    float* As = smem;
    float* Bs = smem + 2 * 128 * 36;
    const uint32_t as_u = smem_u32(As);
    const uint32_t bs_u = smem_u32(Bs);
    const uint32_t bufb = 128 * 36 * 4;
    const uint32_t a_base = as_u + (uint32_t)((warpM * 32 + arow) * 36 + akof) * 4;
    const uint32_t b_base = bs_u + (uint32_t)((warpN * 64 + brow) * 36 + bkof) * 4;

    gemm_stage(as_u, bs_u, Ag, Bg, 0, tid);
    CP_COMMIT();

    for (int ct = 0; ct < C_ / 32; ct++) {
        const int cur = ct & 1;
        if (ct + 1 < C_ / 32) {
            gemm_stage(as_u + (cur ^ 1) * bufb, bs_u + (cur ^ 1) * bufb,
                       Ag, Bg, (ct + 1) * 32, tid);
            CP_COMMIT();
            CP_WAIT1();
        } else {
            CP_WAIT0();
        }
        __syncthreads();
        const uint32_t ab = a_base + cur * bufb;
        const uint32_t bb_ = b_base + cur * bufb;
#pragma unroll
        for (int ks = 0; ks < 4; ks++) {
            const uint32_t k0b = ks * 32;   // 8 floats
            uint32_t a[2][4];
            ldsm4(a[0], ab + k0b);
            ldsm4(a[1], ab + 16 * 36 * 4 + k0b);
#pragma unroll
            for (int ntp = 0; ntp < 4; ntp++) {
                uint32_t bb[4];
                ldsm4(bb, bb_ + (uint32_t)(ntp * 16 * 36) * 4 + k0b);
                mma_tf32(acc[0][2 * ntp],     a[0], bb[0], bb[1]);
                mma_tf32(acc[1][2 * ntp],     a[1], bb[0], bb[1]);
                mma_tf32(acc[0][2 * ntp + 1], a[0], bb[2], bb[3]);
                mma_tf32(acc[1][2 * ntp + 1], a[1], bb[2], bb[3]);
            }
        }
        __syncthreads();
    }
}

// ===========================================================================
// Fused Q,K projections, TRANSPOSED tf32 output [b][l][c].
// ===========================================================================
__global__ __launch_bounds__(256) void qkv_mma(const float* __restrict__ bq,
                                               const float* __restrict__ bk,
                                               const float* __restrict__ XT,
                                               float* __restrict__ q,
                                               float* __restrict__ k) {
    extern __shared__ float smem[];
    const int tid = threadIdx.x;
    const int lane = tid & 31;
    const int g = lane >> 2, tig = lane & 3;
    const int wid = tid >> 5;
    const int warpM = wid & 3, warpN = wid >> 2;
    const int pid = blockIdx.z & 1;
    const int b   = blockIdx.z >> 1;
    const int l0  = blockIdx.y * 128;
    const int o0  = blockIdx.x * 128;

    const float* bias = (pid == 0) ? bq : bk;
    float* Y          = (pid == 0) ? q  : k;
    const float* Ag = XT + ((size_t)b * L_ + l0) * C_;
    const float* Bg = g_wr + (size_t)pid * C_ * C_ + (size_t)o0 * C_;

    float acc[2][8][4];
#pragma unroll
    for (int mt = 0; mt < 2; mt++)
#pragma unroll
        for (int nt = 0; nt < 8; nt++)
#pragma unroll
            for (int i = 0; i < 4; i++) acc[mt][nt][i] = 0.f;

    gemm_core(acc, smem, Ag, Bg, tid);

#pragma unroll
    for (int mt = 0; mt < 2; mt++) {
        int lr0 = l0 + warpM * 32 + mt * 16;
        float* y0 = Y + ((size_t)b * L_ + lr0 + g) * C_;
        float* y1 = Y + ((size_t)b * L_ + lr0 + g + 8) * C_;
#pragma unroll
        for (int nt = 0; nt < 8; nt++) {
            int col = o0 + warpN * 64 + nt * 8 + 2 * tig;
            float bv0 = bias[col], bv1 = bias[col + 1];
            *(float2*)(y0 + col) = make_float2(__uint_as_float(f2tf32(acc[mt][nt][0] + bv0)),
                                               __uint_as_float(f2tf32(acc[mt][nt][1] + bv1)));
            *(float2*)(y1 + col) = make_float2(__uint_as_float(f2tf32(acc[mt][nt][2] + bv0)),
                                               __uint_as_float(f2tf32(acc[mt][nt][3] + bv1)));
        }
    }
}

// ===========================================================================
// V projection, channel-major tf32 output: vCL[b][o][l] = wv.x + bv
// ===========================================================================
__global__ __launch_bounds__(256) void vproj_mma(const float* __restrict__ bias,
                                                 const float* __restrict__ XT,
                                                 float* __restrict__ Y) {
    extern __shared__ float smem[];
    const int tid = threadIdx.x;
    const int lane = tid & 31;
    const int g = lane >> 2, tig = lane & 3;
    const int wid = tid >> 5;
    const int warpM = wid & 3, warpN = wid >> 2;
    const int b  = blockIdx.z;
    const int o0 = blockIdx.y * 128;
    const int l0 = blockIdx.x * 128;

    const float* Ag = g_wr + (size_t)2 * C_ * C_ + (size_t)o0 * C_;
    const float* Bg = XT + ((size_t)b * L_ + l0) * C_;

    float acc[2][8][4];
#pragma unroll
    for (int mt = 0; mt < 2; mt++)
#pragma unroll
        for (int nt = 0; nt < 8; nt++)
#pragma unroll
            for (int i = 0; i < 4; i++) acc[mt][nt][i] = 0.f;

    gemm_core(acc, smem, Ag, Bg, tid);

#pragma unroll
    for (int mt = 0; mt < 2; mt++) {
        int r0 = o0 + warpM * 32 + mt * 16;
        float bv0 = bias[r0 + g];
        float bv1 = bias[r0 + g + 8];
        float* y0 = Y + ((size_t)b * C_ + r0 + g) * L_;
        float* y1 = Y + ((size_t)b * C_ + r0 + g + 8) * L_;
#pragma unroll
        for (int nt = 0; nt < 8; nt++) {
            int col = l0 + warpN * 64 + nt * 8 + 2 * tig;
            *(float2*)(y0 + col) = make_float2(__uint_as_float(f2tf32(acc[mt][nt][0] + bv0)),
                                               __uint_as_float(f2tf32(acc[mt][nt][1] + bv0)));
            *(float2*)(y1 + col) = make_float2(__uint_as_float(f2tf32(acc[mt][nt][2] + bv1)),
                                               __uint_as_float(f2tf32(acc[mt][nt][3] + bv1)));
        }
    }
}

// ===========================================================================
// O projection: out[b][o][l] = sum_c W[o][c] * resT[b][l][c] + bias[o]
// ===========================================================================
__global__ __launch_bounds__(256) void proj_mma(const float* __restrict__ bias,
                                                const float* __restrict__ XT,
                                                float* __restrict__ Y) {
    extern __shared__ float smem[];
    const int tid = threadIdx.x;
    const int lane = tid & 31;
    const int g = lane >> 2, tig = lane & 3;
    const int wid = tid >> 5;
    const int warpM = wid & 3, warpN = wid >> 2;
    const int b  = blockIdx.z;
    const int o0 = blockIdx.y * 128;
    const int l0 = blockIdx.x * 128;

    const float* Ag = g_wr + (size_t)3 * C_ * C_ + (size_t)o0 * C_;
    const float* Bg = XT + ((size_t)b * L_ + l0) * C_;

    float acc[2][8][4];
#pragma unroll
    for (int mt = 0; mt < 2; mt++)
#pragma unroll
        for (int nt = 0; nt < 8; nt++)
#pragma unroll
            for (int i = 0; i < 4; i++) acc[mt][nt][i] = 0.f;

    gemm_core(acc, smem, Ag, Bg, tid);

#pragma unroll
    for (int mt = 0; mt < 2; mt++) {
        int r0 = o0 + warpM * 32 + mt * 16;
        float bv0 = bias[r0 + g];
        float bv1 = bias[r0 + g + 8];
        float* y0 = Y + ((size_t)b * C_ + r0 + g) * L_;
        float* y1 = Y + ((size_t)b * C_ + r0 + g + 8) * L_;
#pragma unroll
        for (int nt = 0; nt < 8; nt++) {
            int col = l0 + warpN * 64 + nt * 8 + 2 * tig;
            *(float2*)(y0 + col) = make_float2(acc[mt][nt][0] + bv0, acc[mt][nt][1] + bv0);
            *(float2*)(y1 + col) = make_float2(acc[mt][nt][2] + bv1, acc[mt][nt][3] + bv1);
        }
    }
}

// ===========================================================================
// Tensor-core flash attention, cp.async double-buffered K/V, ldmatrix
// fragment loads, 2 CTAs/SM.  K smem: [kpos][dim]; V smem: [dim][kpos]
// (cp.async'd from channel-major g_vCL). 128 q-rows; 8 warps.
// ===========================================================================
#define AP 68
#define KVF 4352                 // floats per 64x68 buffer
#define SM_QP  0                 // Q-stage then P: [128][68]
#define SM_K   8704              // 2 x [64][68]
#define SM_V   17408             // 2 x [64][68]
#define SM_EK  26112             // [9][64]
#define SM_EV  26688             // [9][64]
#define SM_QEK 27264             // [128][9]
#define ATTN_SMEMF 28416         // 113664 bytes

__global__ __launch_bounds__(256, 2) void attn_mma(const float* __restrict__ erk,
                                                   const float* __restrict__ erv) {
    extern __shared__ float sm[];
    float* QP  = sm + SM_QP;
    float* Ks  = sm + SM_K;
    float* Vs  = sm + SM_V;
    float* Eks = sm + SM_EK;
    float* Evs = sm + SM_EV;
    float* qEk = sm + SM_QEK;

    const int tid = threadIdx.x;
    const int w = tid >> 5, lane = tid & 31;
    const int g = lane >> 2, tig = lane & 3;
    const int rb = w * 16;
    const int i0 = blockIdx.x * 128;
    const int bh = blockIdx.y;
    const int b = bh / H_, h = bh % H_;

    const int tile = lane >> 3, tr = lane & 7;
    const int arow = ((tile & 1) ? 8 : 0) + tr;
    const int akof = (tile & 2) ? 4 : 0;
    const int brow = ((tile & 2) ? 8 : 0) + tr;
    const int bkof = (tile & 1) ? 4 : 0;

    const float* QT = g_qT + (size_t)b * L_ * C_ + h * D_;
    const float* KT = g_kT + (size_t)b * L_ * C_ + h * D_;
    const float* VC = g_vCL + ((size_t)b * C_ + h * D_) * L_;

    const uint32_t qp_u = smem_u32(QP);
    const uint32_t ks_u = smem_u32(Ks);
    const uint32_t vs_u = smem_u32(Vs);
    const uint32_t kfrag = (uint32_t)(brow * AP + bkof) * 4;              // B-frags (K,V)
    const uint32_t afrag = qp_u + (uint32_t)((rb + arow) * AP + akof) * 4; // P A-frags
    const int cp_r  = tid >> 4;          // 0..15
    const int cp_d4 = (tid & 15) * 4;

    // Prefetch K/V tile 0 into buffer 0. K rows = kpos; V rows = dim.
#pragma unroll
    for (int it = 0; it < 4; it++) {
        int r = it * 16 + cp_r;
        uint32_t so = (uint32_t)(r * AP + cp_d4) * 4;
        cp_async16(ks_u + so, KT + (size_t)r * C_ + cp_d4);
        cp_async16(vs_u + so, VC + (size_t)r * L_ + cp_d4);
    }
    CP_COMMIT();

    // Stage Q (pre-scaled by 1/8, exact) + embedding tables.
#pragma unroll
    for (int it = 0; it < 8; it++) {
        int idx = it * 256 + tid;
        int r = idx >> 4, d4 = (idx & 15) * 4;
        float4 q4 = *(const float4*)(QT + (size_t)(i0 + r) * C_ + d4);
        QP[r * AP + d4 + 0] = q4.x * 0.125f;
        QP[r * AP + d4 + 1] = q4.y * 0.125f;
        QP[r * AP + d4 + 2] = q4.z * 0.125f;
        QP[r * AP + d4 + 3] = q4.w * 0.125f;
    }
    for (int e = tid; e < NW_ * 64; e += 256) {
        int dd = e >> 6, r = e & 63;
        Eks[dd * 64 + r] = erk[(h * NW_ + dd) * 64 + r];
        Evs[dd * 64 + r] = erv[(h * NW_ + dd) * 64 + r];
    }
    __syncthreads();

    // qEk[i][dd] = (q_i/8) . Ek[dd]
    for (int e = tid; e < 128 * NW_; e += 256) {
        int dd = e / 128, i = e % 128;
        float s = 0.f;
#pragma unroll
        for (int d = 0; d < 64; d++) s += QP[i * AP + d] * Eks[dd * 64 + d];
        qEk[i * NW_ + dd] = s;
    }

    // Q fragments into registers.
    uint32_t qf[8][4];
#pragma unroll
    for (int ks = 0; ks < 8; ks++) {
        const int k0 = ks * 8;
        qf[ks][0] = __float_as_uint(QP[(rb + g) * AP + k0 + tig]);
        qf[ks][1] = __float_as_uint(QP[(rb + g + 8) * AP + k0 + tig]);
        qf[ks][2] = __float_as_uint(QP[(rb + g) * AP + k0 + tig + 4]);
        qf[ks][3] = __float_as_uint(QP[(rb + g + 8) * AP + k0 + tig + 4]);
    }

    float m0 = -1e30f, m1 = -1e30f, l0 = 0.f, l1 = 0.f;
    float o[8][4];
#pragma unroll
    for (int nt = 0; nt < 8; nt++)
#pragma unroll
        for (int i = 0; i < 4; i++) o[nt][i] = 0.f;

    const int qi0 = i0 + rb + g;
    const int qi1 = qi0 + 8;
    const int NT = L_ / 64;

    for (int jt = 0; jt < NT; jt++) {
        const int j0 = jt * 64;
        const int cur = jt & 1;
        if (jt + 1 < NT) {
            const float* Kn = KT + (size_t)(j0 + 64) * C_;
            const float* Vn = VC + (size_t)(j0 + 64);
            uint32_t bo = (uint32_t)((cur ^ 1) * KVF) * 4;
#pragma unroll
            for (int it = 0; it < 4; it++) {
                int r = it * 16 + cp_r;
                uint32_t so = bo + (uint32_t)(r * AP + cp_d4) * 4;
                cp_async16(ks_u + so, Kn + (size_t)r * C_ + cp_d4);
                cp_async16(vs_u + so, Vn + (size_t)r * L_ + cp_d4);
            }
            CP_COMMIT();
            CP_WAIT1();
        } else {
            CP_WAIT0();
        }
        __syncthreads();   // K/V visible; qEk + Q-frag hoist fenced (jt=0)

        const uint32_t kcu = ks_u + (uint32_t)(cur * KVF) * 4 + kfrag;
        const uint32_t vcu = vs_u + (uint32_t)(cur * KVF) * 4 + kfrag;

        // S = (Q/8) K^T  — K fragments via ldmatrix.x4
        float s[8][4];
#pragma unroll
        for (int nt = 0; nt < 8; nt++)
#pragma unroll
            for (int i = 0; i < 4; i++) s[nt][i] = 0.f;
#pragma unroll
        for (int ks = 0; ks < 8; ks++) {
            const uint32_t k0b = ks * 32;
#pragma unroll
            for (int ntp = 0; ntp < 4; ntp++) {
                uint32_t bb[4];
                ldsm4(bb, kcu + (uint32_t)(ntp * 16 * AP) * 4 + k0b);
                mma_tf32(s[2 * ntp],     qf[ks], bb[0], bb[1]);
                mma_tf32(s[2 * ntp + 1], qf[ks], bb[2], bb[3]);
            }
        }

        // Relative-K band bias (scale folded into qEk)
        const bool near = (j0 + 63 >= i0 - 4) && (j0 <= i0 + 131);
        if (near) {
#pragma unroll
            for (int nt = 0; nt < 8; nt++) {
#pragma unroll
                for (int c = 0; c < 2; c++) {
                    int j = j0 + nt * 8 + 2 * tig + c;
                    int d0 = j - qi0;
                    if (d0 >= -4 && d0 <= 4) s[nt][c] += qEk[(rb + g) * NW_ + d0 + 4];
                    int d1 = j - qi1;
                    if (d1 >= -4 && d1 <= 4) s[nt][c + 2] += qEk[(rb + g + 8) * NW_ + d1 + 4];
                }
            }
        }

        // Online softmax (4-lane row reductions)
        float tm0 = -1e30f, tm1 = -1e30f;
#pragma unroll
        for (int nt = 0; nt < 8; nt++) {
            tm0 = fmaxf(tm0, fmaxf(s[nt][0], s[nt][1]));
            tm1 = fmaxf(tm1, fmaxf(s[nt][2], s[nt][3]));
        }
#pragma unroll
        for (int off = 1; off <= 2; off <<= 1) {
            tm0 = fmaxf(tm0, __shfl_xor_sync(0xffffffffu, tm0, off));
            tm1 = fmaxf(tm1, __shfl_xor_sync(0xffffffffu, tm1, off));
        }
        float mn0 = fmaxf(m0, tm0), mn1 = fmaxf(m1, tm1);
        float ts0 = 0.f, ts1 = 0.f;
#pragma unroll
        for (int nt = 0; nt < 8; nt++) {
            s[nt][0] = __expf(s[nt][0] - mn0);
            s[nt][1] = __expf(s[nt][1] - mn0);
            s[nt][2] = __expf(s[nt][2] - mn1);
            s[nt][3] = __expf(s[nt][3] - mn1);
            ts0 += s[nt][0] + s[nt][1];
            ts1 += s[nt][2] + s[nt][3];
        }
#pragma unroll
        for (int off = 1; off <= 2; off <<= 1) {
            ts0 += __shfl_xor_sync(0xffffffffu, ts0, off);
            ts1 += __shfl_xor_sync(0xffffffffu, ts1, off);
        }
        float al0 = __expf(m0 - mn0), al1 = __expf(m1 - mn1);
        l0 = l0 * al0 + ts0;  m0 = mn0;
        l1 = l1 * al1 + ts1;  m1 = mn1;
#pragma unroll
        for (int nt = 0; nt < 8; nt++) {
            o[nt][0] *= al0; o[nt][1] *= al0;
            o[nt][2] *= al1; o[nt][3] *= al1;
        }

        // Stage P (tf32-rounded) into warp-private rows of QP.
#pragma unroll
        for (int nt = 0; nt < 8; nt++) {
            int col = nt * 8 + 2 * tig;
            *(float2*)&QP[(rb + g) * AP + col] =
                make_float2(__uint_as_float(f2tf32(s[nt][0])),
                            __uint_as_float(f2tf32(s[nt][1])));
            *(float2*)&QP[(rb + g + 8) * AP + col] =
                make_float2(__uint_as_float(f2tf32(s[nt][2])),
                            __uint_as_float(f2tf32(s[nt][3])));
        }
        __syncwarp();

        // O += P V  — A (P) and B (V^T) fragments via ldmatrix.x4
#pragma unroll
        for (int ks = 0; ks < 8; ks++) {
            const uint32_t k0b = ks * 32;
            uint32_t a[4];
            ldsm4(a, afrag + k0b);
#pragma unroll
            for (int ntp = 0; ntp < 4; ntp++) {
                uint32_t bb[4];
                ldsm4(bb, vcu + (uint32_t)(ntp * 16 * AP) * 4 + k0b);
                mma_tf32(o[2 * ntp],     a, bb[0], bb[1]);
                mma_tf32(o[2 * ntp + 1], a, bb[2], bb[3]);
            }
        }

        // Relative-V band
        if (near) {
#pragma unroll
            for (int dd = 0; dd < NW_; dd++) {
                int j0r = qi0 + dd - 4 - j0;
                if (j0r >= 0 && j0r < 64) {
                    float p = QP[(rb + g) * AP + j0r];
#pragma unroll
                    for (int nt = 0; nt < 8; nt++) {
                        int col = nt * 8 + 2 * tig;
                        o[nt][0] += p * Evs[dd * 64 + col];
                        o[nt][1] += p * Evs[dd * 64 + col + 1];
                    }
                }
                int j1r = qi1 + dd - 4 - j0;
                if (j1r >= 0 && j1r < 64) {
                    float p = QP[(rb + g + 8) * AP + j1r];
#pragma unroll
                    for (int nt = 0; nt < 8; nt++) {
                        int col = nt * 8 + 2 * tig;
                        o[nt][2] += p * Evs[dd * 64 + col];
                        o[nt][3] += p * Evs[dd * 64 + col + 1];
                    }
                }
            }
        }
        __syncthreads();   // all reads of buf cur done before re-prefetch
    }

    // Epilogue: normalize, tf32-round, store resT[b][l][h*64+dim].
    float inv0 = 1.0f / l0, inv1 = 1.0f / l1;
    float* r0p = g_resT + ((size_t)b * L_ + qi0) * C_ + h * D_;
    float* r1p = g_resT + ((size_t)b * L_ + qi1) * C_ + h * D_;
#pragma unroll
    for (int nt = 0; nt < 8; nt++) {
        int col = nt * 8 + 2 * tig;
        *(float2*)(r0p + col) = make_float2(__uint_as_float(f2tf32(o[nt][0] * inv0)),
                                            __uint_as_float(f2tf32(o[nt][1] * inv0)));
        *(float2*)(r1p + col) = make_float2(__uint_as_float(f2tf32(o[nt][2] * inv1)),
                                            __uint_as_float(f2tf32(o[nt][3] * inv1)));
    }
}

// ---------------------------------------------------------------------------
extern "C" void kernel_launch(void* const* d_in, const int* in_sizes, int n_in,
                              void* d_out, int out_size) {
    const float* x   = (const float*)d_in[0];
    const float* wq  = (const float*)d_in[1];
    const float* bq  = (const float*)d_in[2];
    const float* wk  = (const float*)d_in[3];
    const float* bk  = (const float*)d_in[4];
    const float* wv  = (const float*)d_in[5];
    const float* bv  = (const float*)d_in[6];
    const float* wo  = (const float*)d_in[7];
    const float* bo  = (const float*)d_in[8];
    const float* erk = (const float*)d_in[9];
    const float* erv = (const float*)d_in[10];
    float* out = (float*)d_out;

    float *gqT, *gkT, *gvCL, *gxT, *gresT, *gwr;
    cudaGetSymbolAddress((void**)&gqT,   g_qT);
    cudaGetSymbolAddress((void**)&gkT,   g_kT);
    cudaGetSymbolAddress((void**)&gvCL,  g_vCL);
    cudaGetSymbolAddress((void**)&gxT,   g_xT);
    cudaGetSymbolAddress((void**)&gresT, g_resT);
    cudaGetSymbolAddress((void**)&gwr,   g_wr);

    const int attn_smem = ATTN_SMEMF * 4;  // 113664 bytes -> 2 CTAs/SM
    const int gemm_smem = GEMM_SMEMF * 4;  // 73728 bytes
    cudaFuncSetAttribute(attn_mma, cudaFuncAttributeMaxDynamicSharedMemorySize,
                         attn_smem);
    cudaFuncSetAttribute(qkv_mma, cudaFuncAttributeMaxDynamicSharedMemorySize,
                         gemm_smem);
    cudaFuncSetAttribute(vproj_mma, cudaFuncAttributeMaxDynamicSharedMemorySize,
                         gemm_smem);
    cudaFuncSetAttribute(proj_mma, cudaFuncAttributeMaxDynamicSharedMemorySize,
                         gemm_smem);

    // x[b][c][l] -> tf32(xT[b][l][c]); round weights once
    dim3 tgrid(L_ / 32, C_ / 32, B_);
    transpose_kernel<<<tgrid, 256>>>(x, gxT, C_, L_);
    dim3 wgrid(C_ * C_ / 1024, 4);
    round_w<<<wgrid, 256>>>(wq, wk, wv, wo, gwr);

    // Q,K projections (transposed tf32) + V projection (channel-major tf32)
    dim3 qgrid(C_ / 128, L_ / 128, B_ * 2);   // (3, 8, 16)
    qkv_mma<<<qgrid, 256, gemm_smem>>>(bq, bk, gxT, gqT, gkT);
    dim3 vgrid(L_ / 128, C_ / 128, B_);       // (8, 3, 8)
    vproj_mma<<<vgrid, 256, gemm_smem>>>(bv, gxT, gvCL);

    // Tensor-core attention (128 q-rows per block, 2 CTAs/SM)
    dim3 agrid(L_ / 128, B_ * H_);            // (8, 48)
    attn_mma<<<agrid, 256, attn_smem>>>(erk, erv);

    // O projection
    dim3 ogrid(L_ / 128, C_ / 128, B_);       // (8, 3, 8)
    proj_mma<<<ogrid, 256, gemm_smem>>>(bo, gresT, out);
}

// round 14
// speedup vs baseline: 1.4263x; 1.4263x over previous
#include <cuda_runtime.h>
#include <cstdint>

#define B_ 8
#define C_ 384
#define L_ 1024
#define H_ 6
#define D_ 64
#define NW_ 9   // 2*window+1

// Scratch (allocation-free rule: device globals). All [b][l][c] layout.
// g_qT/g_kT have dim-channels PERMUTED within 8-groups: global b -> pos ((b&3)<<1)|(b>>2)
__device__ float g_qT[B_*L_*C_];
__device__ float g_kT[B_*L_*C_];
__device__ float g_vT[B_*L_*C_];
__device__ float g_xT[B_*L_*C_];    // tf32-rounded
__device__ float g_resT[B_*L_*C_];  // tf32-rounded (attn epilogue)
__device__ float g_wr[4*C_*C_];     // tf32-rounded wq,wk,wv,wo

__device__ __forceinline__ uint32_t f2tf32(float f) {
    uint32_t r;
    asm("cvt.rna.tf32.f32 %0, %1;" : "=r"(r) : "f"(f));
    return r;
}

__device__ __forceinline__ void mma_tf32(float* d, const uint32_t* a,
                                         uint32_t b0, uint32_t b1) {
    asm volatile("mma.sync.aligned.m16n8k8.row.col.f32.tf32.tf32.f32 "
                 "{%0,%1,%2,%3}, {%4,%5,%6,%7}, {%8,%9}, {%0,%1,%2,%3};"
                 : "+f"(d[0]), "+f"(d[1]), "+f"(d[2]), "+f"(d[3])
                 : "r"(a[0]), "r"(a[1]), "r"(a[2]), "r"(a[3]),
                   "r"(b0), "r"(b1));
}

__device__ __forceinline__ uint32_t smem_u32(const void* p) {
    uint32_t a;
    asm("{ .reg .u64 t; cvta.to.shared.u64 t, %1; cvt.u32.u64 %0, t; }"
        : "=r"(a) : "l"(p));
    return a;
}
__device__ __forceinline__ void cp_async16(uint32_t s, const void* g) {
    asm volatile("cp.async.cg.shared.global [%0], [%1], 16;" :: "r"(s), "l"(g));
}
#define CP_COMMIT() asm volatile("cp.async.commit_group;" ::: "memory")
#define CP_WAIT1()  asm volatile("cp.async.wait_group 1;" ::: "memory")
#define CP_WAIT0()  asm volatile("cp.async.wait_group 0;" ::: "memory")

// ===========================================================================
// Transpose + tf32 round: dst[b][col][row] = rna_tf32(src[b][row][col]).
// ===========================================================================
__global__ __launch_bounds__(256) void transpose_kernel(const float* __restrict__ src,
                                                        float* __restrict__ dst,
                                                        int rows, int cols) {
    __shared__ float tile[32][33];
    const int b = blockIdx.z;
    const int r0 = blockIdx.y * 32;
    const int c0 = blockIdx.x * 32;
    const int tx = threadIdx.x & 31, ty = threadIdx.x >> 5;
    const float* sb = src + (size_t)b * rows * cols;
    float* db = dst + (size_t)b * rows * cols;
#pragma unroll
    for (int i = 0; i < 4; i++)
        tile[ty + i * 8][tx] = sb[(size_t)(r0 + ty + i * 8) * cols + c0 + tx];
    __syncthreads();
#pragma unroll
    for (int i = 0; i < 4; i++)
        db[(size_t)(c0 + ty + i * 8) * rows + r0 + tx] =
            __uint_as_float(f2tf32(tile[tx][ty + i * 8]));
}

// ===========================================================================
// Round the four weight matrices to tf32 once.
// ===========================================================================
__global__ __launch_bounds__(256) void round_w(const float* __restrict__ w0,
                                               const float* __restrict__ w1,
                                               const float* __restrict__ w2,
                                               const float* __restrict__ w3,
                                               float* __restrict__ dst) {
    const int m = blockIdx.y;
    const float* src = (m == 0) ? w0 : (m == 1) ? w1 : (m == 2) ? w2 : w3;
    int idx = (blockIdx.x * 256 + threadIdx.x) * 4;
    float4 v = *(const float4*)(src + idx);
    uint4 t = make_uint4(f2tf32(v.x), f2tf32(v.y), f2tf32(v.z), f2tf32(v.w));
    *(uint4*)(dst + (size_t)m * C_ * C_ + idx) = t;
}

// ===========================================================================
// cp.async double-buffered tf32 GEMM core (R12-proven, scalar frag loads).
// Tile 128x128, K chunks of 32. Smem: 4 buffers of [128][36].
// ===========================================================================
#define GEMM_SMEMF (4 * 128 * 36)   // 73728 bytes

__device__ __forceinline__ void gemm_stage(uint32_t sa, uint32_t sb,
                                           const float* Ag, const float* Bg,
                                           int c0, int tid) {
    const int r_ = tid >> 3;
    const int u  = (tid & 7) * 4;
#pragma unroll
    for (int it = 0; it < 4; it++) {
        int row = it * 32 + r_;
        uint32_t so = (uint32_t)(row * 36 + u) * 4;
        cp_async16(sa + so, Ag + (size_t)row * C_ + c0 + u);
        cp_async16(sb + so, Bg + (size_t)row * C_ + c0 + u);
    }
}

__device__ __forceinline__ void gemm_core(float acc[2][8][4], float* smem,
                                          const float* Ag, const float* Bg,
                                          int tid) {
    const int lane = tid & 31;
    const int g = lane >> 2, tig = lane & 3;
    const int wid = tid >> 5;
    const int warpM = wid & 3, warpN = wid >> 2;
    float* As = smem;
    float* Bs = smem + 2 * 128 * 36;
    const uint32_t as_u = smem_u32(As);
    const uint32_t bs_u = smem_u32(Bs);
    const uint32_t bufb = 128 * 36 * 4;

    gemm_stage(as_u, bs_u, Ag, Bg, 0, tid);
    CP_COMMIT();

    for (int ct = 0; ct < C_ / 32; ct++) {
        const int cur = ct & 1;
        if (ct + 1 < C_ / 32) {
            gemm_stage(as_u + (cur ^ 1) * bufb, bs_u + (cur ^ 1) * bufb,
                       Ag, Bg, (ct + 1) * 32, tid);
            CP_COMMIT();
            CP_WAIT1();
        } else {
            CP_WAIT0();
        }
        __syncthreads();
        const float* Ac = As + cur * 128 * 36;
        const float* Bc = Bs + cur * 128 * 36;
#pragma unroll
        for (int ks = 0; ks < 4; ks++) {
            const int k0 = ks * 8;
            uint32_t a[2][4];
#pragma unroll
            for (int mt = 0; mt < 2; mt++) {
                int rb = warpM * 32 + mt * 16;
                a[mt][0] = __float_as_uint(Ac[(rb + g) * 36 + k0 + tig]);
                a[mt][1] = __float_as_uint(Ac[(rb + g + 8) * 36 + k0 + tig]);
                a[mt][2] = __float_as_uint(Ac[(rb + g) * 36 + k0 + tig + 4]);
                a[mt][3] = __float_as_uint(Ac[(rb + g + 8) * 36 + k0 + tig + 4]);
            }
#pragma unroll
            for (int nt = 0; nt < 8; nt++) {
                int nb = warpN * 64 + nt * 8;
                uint32_t b0 = __float_as_uint(Bc[(nb + g) * 36 + k0 + tig]);
                uint32_t b1 = __float_as_uint(Bc[(nb + g) * 36 + k0 + tig + 4]);
#pragma unroll
                for (int mt = 0; mt < 2; mt++)
                    mma_tf32(acc[mt][nt], a[mt], b0, b1);
            }
        }
        __syncthreads();
    }
}

// ===========================================================================
// Fused QKV projection, TRANSPOSED tf32 output [b][l][c].
// q,k outputs have dim-channels permuted within 8-groups (pos(b)); v unpermuted.
// ===========================================================================
__global__ __launch_bounds__(256) void qkv_mma(const float* __restrict__ bq,
                                               const float* __restrict__ bk,
                                               const float* __restrict__ bv,
                                               const float* __restrict__ XT,
                                               float* __restrict__ q,
                                               float* __restrict__ k,
                                               float* __restrict__ v) {
    extern __shared__ float smem[];
    const int tid = threadIdx.x;
    const int lane = tid & 31;
    const int g = lane >> 2, tig = lane & 3;
    const int wid = tid >> 5;
    const int warpM = wid & 3, warpN = wid >> 2;
    const int pid = blockIdx.z % 3;
    const int b   = blockIdx.z / 3;
    const int l0  = blockIdx.y * 128;
    const int o0  = blockIdx.x * 128;

    const float* bias = (pid == 0) ? bq : (pid == 1) ? bk : bv;
    float* Y          = (pid == 0) ? q  : (pid == 1) ? k  : v;
    const float* Ag = XT + ((size_t)b * L_ + l0) * C_;
    const float* Bg = g_wr + (size_t)pid * C_ * C_ + (size_t)o0 * C_;

    float acc[2][8][4];
#pragma unroll
    for (int mt = 0; mt < 2; mt++)
#pragma unroll
        for (int nt = 0; nt < 8; nt++)
#pragma unroll
            for (int i = 0; i < 4; i++) acc[mt][nt][i] = 0.f;

    gemm_core(acc, smem, Ag, Bg, tid);

    // channel positions within 8-group: global b -> pos(b) = ((b&3)<<1)|(b>>2)
    const int b0g = 2 * tig, b1g = 2 * tig + 1;
    const int p0 = ((b0g & 3) << 1) | (b0g >> 2);
    const int p1 = ((b1g & 3) << 1) | (b1g >> 2);

#pragma unroll
    for (int mt = 0; mt < 2; mt++) {
        int lr0 = l0 + warpM * 32 + mt * 16;
        float* y0 = Y + ((size_t)b * L_ + lr0 + g) * C_;
        float* y1 = Y + ((size_t)b * L_ + lr0 + g + 8) * C_;
#pragma unroll
        for (int nt = 0; nt < 8; nt++) {
            int grp = o0 + warpN * 64 + nt * 8;
            float bv0 = bias[grp + b0g], bv1 = bias[grp + b1g];
            float v0 = __uint_as_float(f2tf32(acc[mt][nt][0] + bv0));
            float v1 = __uint_as_float(f2tf32(acc[mt][nt][1] + bv1));
            float v2 = __uint_as_float(f2tf32(acc[mt][nt][2] + bv0));
            float v3 = __uint_as_float(f2tf32(acc[mt][nt][3] + bv1));
            if (pid < 2) {  // permuted scalar stores for q,k
                y0[grp + p0] = v0;  y0[grp + p1] = v1;
                y1[grp + p0] = v2;  y1[grp + p1] = v3;
            } else {        // v: unpermuted float2
                *(float2*)(y0 + grp + b0g) = make_float2(v0, v1);
                *(float2*)(y1 + grp + b0g) = make_float2(v2, v3);
            }
        }
    }
}

// ===========================================================================
// O projection: out[b][o][l] = sum_c W[o][c] * resT[b][l][c] + bias[o]
// ===========================================================================
__global__ __launch_bounds__(256) void proj_mma(const float* __restrict__ bias,
                                                const float* __restrict__ XT,
                                                float* __restrict__ Y) {
    extern __shared__ float smem[];
    const int tid = threadIdx.x;
    const int lane = tid & 31;
    const int g = lane >> 2, tig = lane & 3;
    const int wid = tid >> 5;
    const int warpM = wid & 3, warpN = wid >> 2;
    const int b  = blockIdx.z;
    const int o0 = blockIdx.y * 128;
    const int l0 = blockIdx.x * 128;

    const float* Ag = g_wr + (size_t)3 * C_ * C_ + (size_t)o0 * C_;
    const float* Bg = XT + ((size_t)b * L_ + l0) * C_;

    float acc[2][8][4];
#pragma unroll
    for (int mt = 0; mt < 2; mt++)
#pragma unroll
        for (int nt = 0; nt < 8; nt++)
#pragma unroll
            for (int i = 0; i < 4; i++) acc[mt][nt][i] = 0.f;

    gemm_core(acc, smem, Ag, Bg, tid);

#pragma unroll
    for (int mt = 0; mt < 2; mt++) {
        int r0 = o0 + warpM * 32 + mt * 16;
        float bv0 = bias[r0 + g];
        float bv1 = bias[r0 + g + 8];
        float* y0 = Y + ((size_t)b * C_ + r0 + g) * L_;
        float* y1 = Y + ((size_t)b * C_ + r0 + g + 8) * L_;
#pragma unroll
        for (int nt = 0; nt < 8; nt++) {
            int col = l0 + warpN * 64 + nt * 8 + 2 * tig;
            *(float2*)(y0 + col) = make_float2(acc[mt][nt][0] + bv0, acc[mt][nt][1] + bv0);
            *(float2*)(y1 + col) = make_float2(acc[mt][nt][2] + bv1, acc[mt][nt][3] + bv1);
        }
    }
}

// ===========================================================================
// Tensor-core flash attention, cp.async double-buffered K/V, 2 CTAs/SM.
// Block: 128 q-rows of one (b,h); 8 warps; warp = 16 rows x 64 cols.
// Q/K global arrays are dim-permuted: K fragment (b0,b1) = one float2;
// mma slots receive identical global-k as R12 => QK bit-identical.
// K smem stride 72 (conflict-free float2); QP/V stride 68 (R12-proven).
// ===========================================================================
#define AP 68
#define APK 72
#define KVF_V 4352               // floats per V buffer (64*68)
#define KVF_K 4608               // floats per K buffer (64*72)
#define SM_QP  0                 // Q-stage then P: [128][68] = 8704
#define SM_K   8704              // 2 x [64][72]   = 9216
#define SM_V   17920             // 2 x [64][68]   = 8704
#define SM_EK  26624             // [9][64] = 576
#define SM_EV  27200             // [9][64] = 576
#define SM_QEK 27776             // [128][9] = 1152
#define ATTN_SMEMF 28928         // 115712 bytes

__global__ __launch_bounds__(256, 2) void attn_mma(const float* __restrict__ erk,
                                                   const float* __restrict__ erv) {
    extern __shared__ float sm[];
    float* QP  = sm + SM_QP;
    float* Ks  = sm + SM_K;
    float* Vs  = sm + SM_V;
    float* Eks = sm + SM_EK;
    float* Evs = sm + SM_EV;
    float* qEk = sm + SM_QEK;

    const int tid = threadIdx.x;
    const int w = tid >> 5, lane = tid & 31;
    const int g = lane >> 2, tig = lane & 3;
    const int rb = w * 16;
    const int i0 = blockIdx.x * 128;
    const int bh = blockIdx.y;
    const int b = bh / H_, h = bh % H_;

    const float* QT = g_qT + (size_t)b * L_ * C_ + h * D_;
    const float* KT = g_kT + (size_t)b * L_ * C_ + h * D_;
    const float* VT = g_vT + (size_t)b * L_ * C_ + h * D_;

    const uint32_t ks_u = smem_u32(Ks);
    const uint32_t vs_u = smem_u32(Vs);
    const int cp_r  = tid >> 4;          // 0..15
    const int cp_d4 = (tid & 15) * 4;

    // Prefetch K/V tile 0 into buffer 0.
#pragma unroll
    for (int it = 0; it < 4; it++) {
        int r = it * 16 + cp_r;
        cp_async16(ks_u + (uint32_t)(r * APK + cp_d4) * 4, KT + (size_t)r * C_ + cp_d4);
        cp_async16(vs_u + (uint32_t)(r * AP  + cp_d4) * 4, VT + (size_t)r * C_ + cp_d4);
    }
    CP_COMMIT();

    // Stage Q (pre-scaled by 1/8, exact; already dim-permuted in global).
#pragma unroll
    for (int it = 0; it < 8; it++) {
        int idx = it * 256 + tid;
        int r = idx >> 4, d4 = (idx & 15) * 4;
        float4 q4 = *(const float4*)(QT + (size_t)(i0 + r) * C_ + d4);
        QP[r * AP + d4 + 0] = q4.x * 0.125f;
        QP[r * AP + d4 + 1] = q4.y * 0.125f;
        QP[r * AP + d4 + 2] = q4.z * 0.125f;
        QP[r * AP + d4 + 3] = q4.w * 0.125f;
    }
    for (int e = tid; e < NW_ * 64; e += 256) {
        int dd = e >> 6, r = e & 63;
        Eks[dd * 64 + r] = erk[(h * NW_ + dd) * 64 + r];
        Evs[dd * 64 + r] = erv[(h * NW_ + dd) * 64 + r];
    }
    __syncthreads();

    // qEk[i][dd] = (q_i/8) . Ek[dd]; iterate GLOBAL d order through the
    // permutation so the sum order is bit-identical to R12.
    for (int e = tid; e < 128 * NW_; e += 256) {
        int dd = e / 128, i = e % 128;
        float s = 0.f;
#pragma unroll
        for (int d = 0; d < 64; d++) {
            int pos = (d & ~7) | (((d & 3) << 1) | ((d & 7) >> 2));
            s += QP[i * AP + pos] * Eks[dd * 64 + d];
        }
        qEk[i * NW_ + dd] = s;
    }

    // Q fragments into registers: permuted layout makes (k=tig, k=tig+4) an
    // adjacent float2 at col k0 + 2*tig.
    uint32_t qf[8][4];
#pragma unroll
    for (int ks = 0; ks < 8; ks++) {
        const int k0 = ks * 8;
        float2 qa = *(const float2*)&QP[(rb + g) * AP + k0 + 2 * tig];
        float2 qb = *(const float2*)&QP[(rb + g + 8) * AP + k0 + 2 * tig];
        qf[ks][0] = __float_as_uint(qa.x);
        qf[ks][1] = __float_as_uint(qb.x);
        qf[ks][2] = __float_as_uint(qa.y);
        qf[ks][3] = __float_as_uint(qb.y);
    }

    float m0 = -1e30f, m1 = -1e30f, l0 = 0.f, l1 = 0.f;
    float o[8][4];
#pragma unroll
    for (int nt = 0; nt < 8; nt++)
#pragma unroll
        for (int i = 0; i < 4; i++) o[nt][i] = 0.f;

    const int qi0 = i0 + rb + g;
    const int qi1 = qi0 + 8;
    const int NT = L_ / 64;

    for (int jt = 0; jt < NT; jt++) {
        const int j0 = jt * 64;
        const int cur = jt & 1;
        if (jt + 1 < NT) {
            const float* Kn = KT + (size_t)(j0 + 64) * C_;
            const float* Vn = VT + (size_t)(j0 + 64) * C_;
#pragma unroll
            for (int it = 0; it < 4; it++) {
                int r = it * 16 + cp_r;
                cp_async16(ks_u + (uint32_t)((cur ^ 1) * KVF_K + r * APK + cp_d4) * 4,
                           Kn + (size_t)r * C_ + cp_d4);
                cp_async16(vs_u + (uint32_t)((cur ^ 1) * KVF_V + r * AP + cp_d4) * 4,
                           Vn + (size_t)r * C_ + cp_d4);
            }
            CP_COMMIT();
            CP_WAIT1();
        } else {
            CP_WAIT0();
        }
        __syncthreads();   // K/V visible; qEk + Q-frag hoist fenced (jt=0)

        const float* Kc = Ks + cur * KVF_K;
        const float* Vc = Vs + cur * KVF_V;

        // S = (Q/8) K^T — K fragment (b0,b1) as one float2 (permuted layout)
        float s[8][4];
#pragma unroll
        for (int nt = 0; nt < 8; nt++)
#pragma unroll
            for (int i = 0; i < 4; i++) s[nt][i] = 0.f;
#pragma unroll
        for (int ks = 0; ks < 8; ks++) {
            const int k0 = ks * 8;
#pragma unroll
            for (int nt = 0; nt < 8; nt++) {
                float2 kk = *(const float2*)&Kc[(nt * 8 + g) * APK + k0 + 2 * tig];
                mma_tf32(s[nt], qf[ks], __float_as_uint(kk.x), __float_as_uint(kk.y));
            }
        }

        // Relative-K band bias (scale folded into qEk)
        const bool near = (j0 + 63 >= i0 - 4) && (j0 <= i0 + 131);
        if (near) {
#pragma unroll
            for (int nt = 0; nt < 8; nt++) {
#pragma unroll
                for (int c = 0; c < 2; c++) {
                    int j = j0 + nt * 8 + 2 * tig + c;
                    int d0 = j - qi0;
                    if (d0 >= -4 && d0 <= 4) s[nt][c] += qEk[(rb + g) * NW_ + d0 + 4];
                    int d1 = j - qi1;
                    if (d1 >= -4 && d1 <= 4) s[nt][c + 2] += qEk[(rb + g + 8) * NW_ + d1 + 4];
                }
            }
        }

        // Online softmax (4-lane row reductions)
        float tm0 = -1e30f, tm1 = -1e30f;
#pragma unroll
        for (int nt = 0; nt < 8; nt++) {
            tm0 = fmaxf(tm0, fmaxf(s[nt][0], s[nt][1]));
            tm1 = fmaxf(tm1, fmaxf(s[nt][2], s[nt][3]));
        }
#pragma unroll
        for (int off = 1; off <= 2; off <<= 1) {
            tm0 = fmaxf(tm0, __shfl_xor_sync(0xffffffffu, tm0, off));
            tm1 = fmaxf(tm1, __shfl_xor_sync(0xffffffffu, tm1, off));
        }
        float mn0 = fmaxf(m0, tm0), mn1 = fmaxf(m1, tm1);
        float ts0 = 0.f, ts1 = 0.f;
#pragma unroll
        for (int nt = 0; nt < 8; nt++) {
            s[nt][0] = __expf(s[nt][0] - mn0);
            s[nt][1] = __expf(s[nt][1] - mn0);
            s[nt][2] = __expf(s[nt][2] - mn1);
            s[nt][3] = __expf(s[nt][3] - mn1);
            ts0 += s[nt][0] + s[nt][1];
            ts1 += s[nt][2] + s[nt][3];
        }
#pragma unroll
        for (int off = 1; off <= 2; off <<= 1) {
            ts0 += __shfl_xor_sync(0xffffffffu, ts0, off);
            ts1 += __shfl_xor_sync(0xffffffffu, ts1, off);
        }
        float al0 = __expf(m0 - mn0), al1 = __expf(m1 - mn1);
        l0 = l0 * al0 + ts0;  m0 = mn0;
        l1 = l1 * al1 + ts1;  m1 = mn1;
#pragma unroll
        for (int nt = 0; nt < 8; nt++) {
            o[nt][0] *= al0; o[nt][1] *= al0;
            o[nt][2] *= al1; o[nt][3] *= al1;
        }

        // Stage P (tf32-rounded) into warp-private rows of QP (unpermuted cols).
#pragma unroll
        for (int nt = 0; nt < 8; nt++) {
            int col = nt * 8 + 2 * tig;
            *(float2*)&QP[(rb + g) * AP + col] =
                make_float2(__uint_as_float(f2tf32(s[nt][0])),
                            __uint_as_float(f2tf32(s[nt][1])));
            *(float2*)&QP[(rb + g + 8) * AP + col] =
                make_float2(__uint_as_float(f2tf32(s[nt][2])),
                            __uint_as_float(f2tf32(s[nt][3])));
        }
        __syncwarp();

        // O += P V
#pragma unroll
        for (int ks = 0; ks < 8; ks++) {
            const int k0 = ks * 8;
            uint32_t a[4];
            a[0] = __float_as_uint(QP[(rb + g) * AP + k0 + tig]);
            a[1] = __float_as_uint(QP[(rb + g + 8) * AP + k0 + tig]);
            a[2] = __float_as_uint(QP[(rb + g) * AP + k0 + tig + 4]);
            a[3] = __float_as_uint(QP[(rb + g + 8) * AP + k0 + tig + 4]);
#pragma unroll
            for (int nt = 0; nt < 8; nt++) {
                uint32_t b0 = __float_as_uint(Vc[(k0 + tig) * AP + nt * 8 + g]);
                uint32_t b1 = __float_as_uint(Vc[(k0 + tig + 4) * AP + nt * 8 + g]);
                mma_tf32(o[nt], a, b0, b1);
            }
        }

        // Relative-V band
        if (near) {
#pragma unroll
            for (int dd = 0; dd < NW_; dd++) {
                int j0r = qi0 + dd - 4 - j0;
                if (j0r >= 0 && j0r < 64) {
                    float p = QP[(rb + g) * AP + j0r];
#pragma unroll
                    for (int nt = 0; nt < 8; nt++) {
                        int col = nt * 8 + 2 * tig;
                        o[nt][0] += p * Evs[dd * 64 + col];
                        o[nt][1] += p * Evs[dd * 64 + col + 1];
                    }
                }
                int j1r = qi1 + dd - 4 - j0;
                if (j1r >= 0 && j1r < 64) {
                    float p = QP[(rb + g + 8) * AP + j1r];
#pragma unroll
                    for (int nt = 0; nt < 8; nt++) {
                        int col = nt * 8 + 2 * tig;
                        o[nt][2] += p * Evs[dd * 64 + col];
                        o[nt][3] += p * Evs[dd * 64 + col + 1];
                    }
                }
            }
        }
        __syncthreads();   // all reads of buf cur done before re-prefetch
    }

    // Epilogue: normalize, tf32-round, store resT[b][l][h*64+dim].
    float inv0 = 1.0f / l0, inv1 = 1.0f / l1;
    float* r0p = g_resT + ((size_t)b * L_ + qi0) * C_ + h * D_;
    float* r1p = g_resT + ((size_t)b * L_ + qi1) * C_ + h * D_;
#pragma unroll
    for (int nt = 0; nt < 8; nt++) {
        int col = nt * 8 + 2 * tig;
        *(float2*)(r0p + col) = make_float2(__uint_as_float(f2tf32(o[nt][0] * inv0)),
                                            __uint_as_float(f2tf32(o[nt][1] * inv0)));
        *(float2*)(r1p + col) = make_float2(__uint_as_float(f2tf32(o[nt][2] * inv1)),
                                            __uint_as_float(f2tf32(o[nt][3] * inv1)));
    }
}

// ---------------------------------------------------------------------------
extern "C" void kernel_launch(void* const* d_in, const int* in_sizes, int n_in,
                              void* d_out, int out_size) {
    const float* x   = (const float*)d_in[0];
    const float* wq  = (const float*)d_in[1];
    const float* bq  = (const float*)d_in[2];
    const float* wk  = (const float*)d_in[3];
    const float* bk  = (const float*)d_in[4];
    const float* wv  = (const float*)d_in[5];
    const float* bv  = (const float*)d_in[6];
    const float* wo  = (const float*)d_in[7];
    const float* bo  = (const float*)d_in[8];
    const float* erk = (const float*)d_in[9];
    const float* erv = (const float*)d_in[10];
    float* out = (float*)d_out;

    float *gqT, *gkT, *gvT, *gxT, *gresT, *gwr;
    cudaGetSymbolAddress((void**)&gqT,   g_qT);
    cudaGetSymbolAddress((void**)&gkT,   g_kT);
    cudaGetSymbolAddress((void**)&gvT,   g_vT);
    cudaGetSymbolAddress((void**)&gxT,   g_xT);
    cudaGetSymbolAddress((void**)&gresT, g_resT);
    cudaGetSymbolAddress((void**)&gwr,   g_wr);

    const int attn_smem = ATTN_SMEMF * 4;  // 115712 bytes -> 2 CTAs/SM
    const int gemm_smem = GEMM_SMEMF * 4;  // 73728 bytes
    cudaFuncSetAttribute(attn_mma, cudaFuncAttributeMaxDynamicSharedMemorySize,
                         attn_smem);
    cudaFuncSetAttribute(qkv_mma, cudaFuncAttributeMaxDynamicSharedMemorySize,
                         gemm_smem);
    cudaFuncSetAttribute(proj_mma, cudaFuncAttributeMaxDynamicSharedMemorySize,
                         gemm_smem);

    // x[b][c][l] -> tf32(xT[b][l][c]); round weights once
    dim3 tgrid(L_ / 32, C_ / 32, B_);
    transpose_kernel<<<tgrid, 256>>>(x, gxT, C_, L_);
    dim3 wgrid(C_ * C_ / 1024, 4);
    round_w<<<wgrid, 256>>>(wq, wk, wv, wo, gwr);

    // Fused QKV (q,k dim-permuted; v unpermuted), cp.async pipelined
    dim3 qgrid(C_ / 128, L_ / 128, B_ * 3);   // (3, 8, 24)
    qkv_mma<<<qgrid, 256, gemm_smem>>>(bq, bk, bv, gxT, gqT, gkT, gvT);

    // Tensor-core attention (128 q-rows per block, 2 CTAs/SM)
    dim3 agrid(L_ / 128, B_ * H_);            // (8, 48)
    attn_mma<<<agrid, 256, attn_smem>>>(erk, erv);

    // O projection (cp.async pipelined)
    dim3 ogrid(L_ / 128, C_ / 128, B_);       // (8, 3, 8)
    proj_mma<<<ogrid, 256, gemm_smem>>>(bo, gresT, out);
}

// round 15
// speedup vs baseline: 1.5144x; 1.0617x over previous
#include <cuda_runtime.h>
#include <cstdint>

#define B_ 8
#define C_ 384
#define L_ 1024
#define H_ 6
#define D_ 64
#define NW_ 9   // 2*window+1

// Scratch (allocation-free rule: device globals).
// g_qT/g_kT: [b][l][c], dim-channels permuted within 8-groups (pos(b)).
// g_vCL:    [b][c][l], kpos (l) permuted within 8-groups (pos(l&7)).
__device__ float g_qT[B_*L_*C_];
__device__ float g_kT[B_*L_*C_];
__device__ float g_vCL[B_*C_*L_];
__device__ float g_xT[B_*L_*C_];    // tf32-rounded
__device__ float g_resT[B_*L_*C_];  // tf32-rounded (attn epilogue)
__device__ float g_wr[4*C_*C_];     // tf32-rounded wq,wk,wv,wo

__device__ __forceinline__ uint32_t f2tf32(float f) {
    uint32_t r;
    asm("cvt.rna.tf32.f32 %0, %1;" : "=r"(r) : "f"(f));
    return r;
}

__device__ __forceinline__ void mma_tf32(float* d, const uint32_t* a,
                                         uint32_t b0, uint32_t b1) {
    asm volatile("mma.sync.aligned.m16n8k8.row.col.f32.tf32.tf32.f32 "
                 "{%0,%1,%2,%3}, {%4,%5,%6,%7}, {%8,%9}, {%0,%1,%2,%3};"
                 : "+f"(d[0]), "+f"(d[1]), "+f"(d[2]), "+f"(d[3])
                 : "r"(a[0]), "r"(a[1]), "r"(a[2]), "r"(a[3]),
                   "r"(b0), "r"(b1));
}

__device__ __forceinline__ uint32_t smem_u32(const void* p) {
    uint32_t a;
    asm("{ .reg .u64 t; cvta.to.shared.u64 t, %1; cvt.u32.u64 %0, t; }"
        : "=r"(a) : "l"(p));
    return a;
}
__device__ __forceinline__ void cp_async16(uint32_t s, const void* g) {
    asm volatile("cp.async.cg.shared.global [%0], [%1], 16;" :: "r"(s), "l"(g));
}
#define CP_COMMIT() asm volatile("cp.async.commit_group;" ::: "memory")
#define CP_WAIT1()  asm volatile("cp.async.wait_group 1;" ::: "memory")
#define CP_WAIT0()  asm volatile("cp.async.wait_group 0;" ::: "memory")

// position of element j within its 8-group after the permutation
__device__ __forceinline__ int posm(int j) { return ((j & 3) << 1) | ((j & 7) >> 2); }

// ===========================================================================
// Transpose + tf32 round: dst[b][col][row] = rna_tf32(src[b][row][col]).
// ===========================================================================
__global__ __launch_bounds__(256) void transpose_kernel(const float* __restrict__ src,
                                                        float* __restrict__ dst,
                                                        int rows, int cols) {
    __shared__ float tile[32][33];
    const int b = blockIdx.z;
    const int r0 = blockIdx.y * 32;
    const int c0 = blockIdx.x * 32;
    const int tx = threadIdx.x & 31, ty = threadIdx.x >> 5;
    const float* sb = src + (size_t)b * rows * cols;
    float* db = dst + (size_t)b * rows * cols;
#pragma unroll
    for (int i = 0; i < 4; i++)
        tile[ty + i * 8][tx] = sb[(size_t)(r0 + ty + i * 8) * cols + c0 + tx];
    __syncthreads();
#pragma unroll
    for (int i = 0; i < 4; i++)
        db[(size_t)(c0 + ty + i * 8) * rows + r0 + tx] =
            __uint_as_float(f2tf32(tile[tx][ty + i * 8]));
}

// ===========================================================================
// Round the four weight matrices to tf32 once.
// ===========================================================================
__global__ __launch_bounds__(256) void round_w(const float* __restrict__ w0,
                                               const float* __restrict__ w1,
                                               const float* __restrict__ w2,
                                               const float* __restrict__ w3,
                                               float* __restrict__ dst) {
    const int m = blockIdx.y;
    const float* src = (m == 0) ? w0 : (m == 1) ? w1 : (m == 2) ? w2 : w3;
    int idx = (blockIdx.x * 256 + threadIdx.x) * 4;
    float4 v = *(const float4*)(src + idx);
    uint4 t = make_uint4(f2tf32(v.x), f2tf32(v.y), f2tf32(v.z), f2tf32(v.w));
    *(uint4*)(dst + (size_t)m * C_ * C_ + idx) = t;
}

// ===========================================================================
// cp.async double-buffered tf32 GEMM core (R12-proven).
// ===========================================================================
#define GEMM_SMEMF (4 * 128 * 36)   // 73728 bytes

__device__ __forceinline__ void gemm_stage(uint32_t sa, uint32_t sb,
                                           const float* Ag, const float* Bg,
                                           int c0, int tid) {
    const int r_ = tid >> 3;
    const int u  = (tid & 7) * 4;
#pragma unroll
    for (int it = 0; it < 4; it++) {
        int row = it * 32 + r_;
        uint32_t so = (uint32_t)(row * 36 + u) * 4;
        cp_async16(sa + so, Ag + (size_t)row * C_ + c0 + u);
        cp_async16(sb + so, Bg + (size_t)row * C_ + c0 + u);
    }
}

__device__ __forceinline__ void gemm_core(float acc[2][8][4], float* smem,
                                          const float* Ag, const float* Bg,
                                          int tid) {
    const int lane = tid & 31;
    const int g = lane >> 2, tig = lane & 3;
    const int wid = tid >> 5;
    const int warpM = wid & 3, warpN = wid >> 2;
    float* As = smem;
    float* Bs = smem + 2 * 128 * 36;
    const uint32_t as_u = smem_u32(As);
    const uint32_t bs_u = smem_u32(Bs);
    const uint32_t bufb = 128 * 36 * 4;

    gemm_stage(as_u, bs_u, Ag, Bg, 0, tid);
    CP_COMMIT();

    for (int ct = 0; ct < C_ / 32; ct++) {
        const int cur = ct & 1;
        if (ct + 1 < C_ / 32) {
            gemm_stage(as_u + (cur ^ 1) * bufb, bs_u + (cur ^ 1) * bufb,
                       Ag, Bg, (ct + 1) * 32, tid);
            CP_COMMIT();
            CP_WAIT1();
        } else {
            CP_WAIT0();
        }
        __syncthreads();
        const float* Ac = As + cur * 128 * 36;
        const float* Bc = Bs + cur * 128 * 36;
#pragma unroll
        for (int ks = 0; ks < 4; ks++) {
            const int k0 = ks * 8;
            uint32_t a[2][4];
#pragma unroll
            for (int mt = 0; mt < 2; mt++) {
                int rb = warpM * 32 + mt * 16;
                a[mt][0] = __float_as_uint(Ac[(rb + g) * 36 + k0 + tig]);
                a[mt][1] = __float_as_uint(Ac[(rb + g + 8) * 36 + k0 + tig]);
                a[mt][2] = __float_as_uint(Ac[(rb + g) * 36 + k0 + tig + 4]);
                a[mt][3] = __float_as_uint(Ac[(rb + g + 8) * 36 + k0 + tig + 4]);
            }
#pragma unroll
            for (int nt = 0; nt < 8; nt++) {
                int nb = warpN * 64 + nt * 8;
                uint32_t b0 = __float_as_uint(Bc[(nb + g) * 36 + k0 + tig]);
                uint32_t b1 = __float_as_uint(Bc[(nb + g) * 36 + k0 + tig + 4]);
#pragma unroll
                for (int mt = 0; mt < 2; mt++)
                    mma_tf32(acc[mt][nt], a[mt], b0, b1);
            }
        }
        __syncthreads();
    }
}

// ===========================================================================
// Fused QKV projection. q,k: [b][l][c] dim-permuted. v: [b][c][l] l-permuted.
// ===========================================================================
__global__ __launch_bounds__(256) void qkv_mma(const float* __restrict__ bq,
                                               const float* __restrict__ bk,
                                               const float* __restrict__ bv,
                                               const float* __restrict__ XT,
                                               float* __restrict__ q,
                                               float* __restrict__ k,
                                               float* __restrict__ v) {
    extern __shared__ float smem[];
    const int tid = threadIdx.x;
    const int lane = tid & 31;
    const int g = lane >> 2, tig = lane & 3;
    const int wid = tid >> 5;
    const int warpM = wid & 3, warpN = wid >> 2;
    const int pid = blockIdx.z % 3;
    const int b   = blockIdx.z / 3;
    const int l0  = blockIdx.y * 128;
    const int o0  = blockIdx.x * 128;

    const float* bias = (pid == 0) ? bq : (pid == 1) ? bk : bv;
    float* Y          = (pid == 0) ? q  : (pid == 1) ? k  : v;
    const float* Ag = XT + ((size_t)b * L_ + l0) * C_;
    const float* Bg = g_wr + (size_t)pid * C_ * C_ + (size_t)o0 * C_;

    float acc[2][8][4];
#pragma unroll
    for (int mt = 0; mt < 2; mt++)
#pragma unroll
        for (int nt = 0; nt < 8; nt++)
#pragma unroll
            for (int i = 0; i < 4; i++) acc[mt][nt][i] = 0.f;

    gemm_core(acc, smem, Ag, Bg, tid);

    const int b0g = 2 * tig, b1g = 2 * tig + 1;
    const int p0 = posm(b0g), p1 = posm(b1g);
    const int pg = posm(g);   // for v's l-permutation

#pragma unroll
    for (int mt = 0; mt < 2; mt++) {
        int lr0 = l0 + warpM * 32 + mt * 16;
#pragma unroll
        for (int nt = 0; nt < 8; nt++) {
            int grp = o0 + warpN * 64 + nt * 8;
            float bv0 = bias[grp + b0g], bv1 = bias[grp + b1g];
            float v0 = __uint_as_float(f2tf32(acc[mt][nt][0] + bv0));
            float v1 = __uint_as_float(f2tf32(acc[mt][nt][1] + bv1));
            float v2 = __uint_as_float(f2tf32(acc[mt][nt][2] + bv0));
            float v3 = __uint_as_float(f2tf32(acc[mt][nt][3] + bv1));
            if (pid < 2) {  // q,k: [b][l][c], dim-permuted scalar stores
                float* y0 = Y + ((size_t)b * L_ + lr0 + g) * C_;
                float* y1 = Y + ((size_t)b * L_ + lr0 + g + 8) * C_;
                y0[grp + p0] = v0;  y0[grp + p1] = v1;
                y1[grp + p0] = v2;  y1[grp + p1] = v3;
            } else {        // v: [b][c][l], l permuted within 8-groups
                float* ya = Y + ((size_t)b * C_ + grp + b0g) * L_;
                float* yb = Y + ((size_t)b * C_ + grp + b1g) * L_;
                ya[lr0 + pg] = v0;      yb[lr0 + pg] = v1;
                ya[lr0 + 8 + pg] = v2;  yb[lr0 + 8 + pg] = v3;
            }
        }
    }
}

// ===========================================================================
// O projection: out[b][o][l] = sum_c W[o][c] * resT[b][l][c] + bias[o]
// ===========================================================================
__global__ __launch_bounds__(256) void proj_mma(const float* __restrict__ bias,
                                                const float* __restrict__ XT,
                                                float* __restrict__ Y) {
    extern __shared__ float smem[];
    const int tid = threadIdx.x;
    const int lane = tid & 31;
    const int g = lane >> 2, tig = lane & 3;
    const int wid = tid >> 5;
    const int warpM = wid & 3, warpN = wid >> 2;
    const int b  = blockIdx.z;
    const int o0 = blockIdx.y * 128;
    const int l0 = blockIdx.x * 128;

    const float* Ag = g_wr + (size_t)3 * C_ * C_ + (size_t)o0 * C_;
    const float* Bg = XT + ((size_t)b * L_ + l0) * C_;

    float acc[2][8][4];
#pragma unroll
    for (int mt = 0; mt < 2; mt++)
#pragma unroll
        for (int nt = 0; nt < 8; nt++)
#pragma unroll
            for (int i = 0; i < 4; i++) acc[mt][nt][i] = 0.f;

    gemm_core(acc, smem, Ag, Bg, tid);

#pragma unroll
    for (int mt = 0; mt < 2; mt++) {
        int r0 = o0 + warpM * 32 + mt * 16;
        float bv0 = bias[r0 + g];
        float bv1 = bias[r0 + g + 8];
        float* y0 = Y + ((size_t)b * C_ + r0 + g) * L_;
        float* y1 = Y + ((size_t)b * C_ + r0 + g + 8) * L_;
#pragma unroll
        for (int nt = 0; nt < 8; nt++) {
            int col = l0 + warpN * 64 + nt * 8 + 2 * tig;
            *(float2*)(y0 + col) = make_float2(acc[mt][nt][0] + bv0, acc[mt][nt][1] + bv0);
            *(float2*)(y1 + col) = make_float2(acc[mt][nt][2] + bv1, acc[mt][nt][3] + bv1);
        }
    }
}

// ===========================================================================
// Tensor-core flash attention, cp.async double-buffered K/V, 2 CTAs/SM.
// Q/K dim-permuted (float2 frags); V channel-major with kpos-permutation
// (float2 B-frags, stride 72 conflict-free); P staged at permuted columns
// (float2 A-frags). mma slots receive identical global-k => bit-identical.
// ===========================================================================
#define AP  68                   // QP stride
#define APK 72                   // K & V smem stride
#define KVF 4608                 // floats per 64x72 buffer
#define SM_QP  0                 // Q-stage then P: [128][68] = 8704
#define SM_K   8704              // 2 x [64][72]   = 9216
#define SM_V   17920             // 2 x [64][72]   = 9216
#define SM_EV  27136             // [9][64] = 576
#define SM_QEK 27712             // [128][9] = 1152
#define ATTN_SMEMF 28864         // 115456 bytes
// Eks overlaps V buffer 1 (prologue-only; protected by pre-mainloop sync)

__global__ __launch_bounds__(256, 2) void attn_mma(const float* __restrict__ erk,
                                                   const float* __restrict__ erv) {
    extern __shared__ float sm[];
    float* QP  = sm + SM_QP;
    float* Ks  = sm + SM_K;
    float* Vs  = sm + SM_V;
    float* Evs = sm + SM_EV;
    float* qEk = sm + SM_QEK;
    float* Eks = Vs + KVF;       // overlaps V buffer 1 during prologue

    const int tid = threadIdx.x;
    const int w = tid >> 5, lane = tid & 31;
    const int g = lane >> 2, tig = lane & 3;
    const int rb = w * 16;
    const int i0 = blockIdx.x * 128;
    const int bh = blockIdx.y;
    const int b = bh / H_, h = bh % H_;

    const float* QT = g_qT + (size_t)b * L_ * C_ + h * D_;
    const float* KT = g_kT + (size_t)b * L_ * C_ + h * D_;
    const float* VC = g_vCL + ((size_t)b * C_ + h * D_) * L_;

    const uint32_t ks_u = smem_u32(Ks);
    const uint32_t vs_u = smem_u32(Vs);
    const int cp_r  = tid >> 4;          // 0..15
    const int cp_d4 = (tid & 15) * 4;

    // Prefetch K/V tile 0 into buffer 0. K rows = kpos (from g_kT);
    // V rows = dim (from g_vCL, kpos already permuted in global).
#pragma unroll
    for (int it = 0; it < 4; it++) {
        int r = it * 16 + cp_r;
        cp_async16(ks_u + (uint32_t)(r * APK + cp_d4) * 4, KT + (size_t)r * C_ + cp_d4);
        cp_async16(vs_u + (uint32_t)(r * APK + cp_d4) * 4, VC + (size_t)r * L_ + cp_d4);
    }
    CP_COMMIT();

    // Stage Q (pre-scaled by 1/8, exact; dim-permuted in global).
#pragma unroll
    for (int it = 0; it < 8; it++) {
        int idx = it * 256 + tid;
        int r = idx >> 4, d4 = (idx & 15) * 4;
        float4 q4 = *(const float4*)(QT + (size_t)(i0 + r) * C_ + d4);
        QP[r * AP + d4 + 0] = q4.x * 0.125f;
        QP[r * AP + d4 + 1] = q4.y * 0.125f;
        QP[r * AP + d4 + 2] = q4.z * 0.125f;
        QP[r * AP + d4 + 3] = q4.w * 0.125f;
    }
    for (int e = tid; e < NW_ * 64; e += 256) {
        int dd = e >> 6, r = e & 63;
        Eks[dd * 64 + r] = erk[(h * NW_ + dd) * 64 + r];
        Evs[dd * 64 + r] = erv[(h * NW_ + dd) * 64 + r];
    }
    __syncthreads();

    // qEk[i][dd] = (q_i/8) . Ek[dd]; GLOBAL d order through the permutation
    // => bit-identical to R12.
    for (int e = tid; e < 128 * NW_; e += 256) {
        int dd = e / 128, i = e % 128;
        float s = 0.f;
#pragma unroll
        for (int d = 0; d < 64; d++) {
            int pos = (d & ~7) | posm(d);
            s += QP[i * AP + pos] * Eks[dd * 64 + d];
        }
        qEk[i * NW_ + dd] = s;
    }

    // Q fragments: permuted layout => (k=tig, k=tig+4) adjacent float2.
    uint32_t qf[8][4];
#pragma unroll
    for (int ks = 0; ks < 8; ks++) {
        const int k0 = ks * 8;
        float2 qa = *(const float2*)&QP[(rb + g) * AP + k0 + 2 * tig];
        float2 qb = *(const float2*)&QP[(rb + g + 8) * AP + k0 + 2 * tig];
        qf[ks][0] = __float_as_uint(qa.x);
        qf[ks][1] = __float_as_uint(qb.x);
        qf[ks][2] = __float_as_uint(qa.y);
        qf[ks][3] = __float_as_uint(qb.y);
    }
    __syncthreads();   // Eks reads done before V-buf1 prefetch (jt=0);
                       // QP Q-reads done before P staging overwrites it.

    float m0 = -1e30f, m1 = -1e30f, l0 = 0.f, l1 = 0.f;
    float o[8][4];
#pragma unroll
    for (int nt = 0; nt < 8; nt++)
#pragma unroll
        for (int i = 0; i < 4; i++) o[nt][i] = 0.f;

    const int qi0 = i0 + rb + g;
    const int qi1 = qi0 + 8;
    const int NT = L_ / 64;
    // P staging permuted column slots for this lane's two values per nt:
    const int sp0 = posm(2 * tig);       // slot of global col 2tig
    const int sp1 = posm(2 * tig + 1);   // slot of global col 2tig+1

    for (int jt = 0; jt < NT; jt++) {
        const int j0 = jt * 64;
        const int cur = jt & 1;
        if (jt + 1 < NT) {
            const float* Kn = KT + (size_t)(j0 + 64) * C_;
            const float* Vn = VC + (size_t)(j0 + 64);
#pragma unroll
            for (int it = 0; it < 4; it++) {
                int r = it * 16 + cp_r;
                cp_async16(ks_u + (uint32_t)((cur ^ 1) * KVF + r * APK + cp_d4) * 4,
                           Kn + (size_t)r * C_ + cp_d4);
                cp_async16(vs_u + (uint32_t)((cur ^ 1) * KVF + r * APK + cp_d4) * 4,
                           Vn + (size_t)r * L_ + cp_d4);
            }
            CP_COMMIT();
            CP_WAIT1();
        } else {
            CP_WAIT0();
        }
        __syncthreads();

        const float* Kc = Ks + cur * KVF;
        const float* Vc = Vs + cur * KVF;

        // S = (Q/8) K^T — K fragment (b0,b1) as one float2
        float s[8][4];
#pragma unroll
        for (int nt = 0; nt < 8; nt++)
#pragma unroll
            for (int i = 0; i < 4; i++) s[nt][i] = 0.f;
#pragma unroll
        for (int ks = 0; ks < 8; ks++) {
            const int k0 = ks * 8;
#pragma unroll
            for (int nt = 0; nt < 8; nt++) {
                float2 kk = *(const float2*)&Kc[(nt * 8 + g) * APK + k0 + 2 * tig];
                mma_tf32(s[nt], qf[ks], __float_as_uint(kk.x), __float_as_uint(kk.y));
            }
        }

        // Relative-K band bias
        const bool near = (j0 + 63 >= i0 - 4) && (j0 <= i0 + 131);
        if (near) {
#pragma unroll
            for (int nt = 0; nt < 8; nt++) {
#pragma unroll
                for (int c = 0; c < 2; c++) {
                    int j = j0 + nt * 8 + 2 * tig + c;
                    int d0 = j - qi0;
                    if (d0 >= -4 && d0 <= 4) s[nt][c] += qEk[(rb + g) * NW_ + d0 + 4];
                    int d1 = j - qi1;
                    if (d1 >= -4 && d1 <= 4) s[nt][c + 2] += qEk[(rb + g + 8) * NW_ + d1 + 4];
                }
            }
        }

        // Online softmax (4-lane row reductions)
        float tm0 = -1e30f, tm1 = -1e30f;
#pragma unroll
        for (int nt = 0; nt < 8; nt++) {
            tm0 = fmaxf(tm0, fmaxf(s[nt][0], s[nt][1]));
            tm1 = fmaxf(tm1, fmaxf(s[nt][2], s[nt][3]));
        }
#pragma unroll
        for (int off = 1; off <= 2; off <<= 1) {
            tm0 = fmaxf(tm0, __shfl_xor_sync(0xffffffffu, tm0, off));
            tm1 = fmaxf(tm1, __shfl_xor_sync(0xffffffffu, tm1, off));
        }
        float mn0 = fmaxf(m0, tm0), mn1 = fmaxf(m1, tm1);
        float ts0 = 0.f, ts1 = 0.f;
#pragma unroll
        for (int nt = 0; nt < 8; nt++) {
            s[nt][0] = __expf(s[nt][0] - mn0);
            s[nt][1] = __expf(s[nt][1] - mn0);
            s[nt][2] = __expf(s[nt][2] - mn1);
            s[nt][3] = __expf(s[nt][3] - mn1);
            ts0 += s[nt][0] + s[nt][1];
            ts1 += s[nt][2] + s[nt][3];
        }
#pragma unroll
        for (int off = 1; off <= 2; off <<= 1) {
            ts0 += __shfl_xor_sync(0xffffffffu, ts0, off);
            ts1 += __shfl_xor_sync(0xffffffffu, ts1, off);
        }
        float al0 = __expf(m0 - mn0), al1 = __expf(m1 - mn1);
        l0 = l0 * al0 + ts0;  m0 = mn0;
        l1 = l1 * al1 + ts1;  m1 = mn1;
#pragma unroll
        for (int nt = 0; nt < 8; nt++) {
            o[nt][0] *= al0; o[nt][1] *= al0;
            o[nt][2] *= al1; o[nt][3] *= al1;
        }

        // Stage P (tf32-rounded) at PERMUTED columns (global col j -> pos(j)).
#pragma unroll
        for (int nt = 0; nt < 8; nt++) {
            int base0 = (rb + g) * AP + nt * 8;
            int base1 = (rb + g + 8) * AP + nt * 8;
            QP[base0 + sp0] = __uint_as_float(f2tf32(s[nt][0]));
            QP[base0 + sp1] = __uint_as_float(f2tf32(s[nt][1]));
            QP[base1 + sp0] = __uint_as_float(f2tf32(s[nt][2]));
            QP[base1 + sp1] = __uint_as_float(f2tf32(s[nt][3]));
        }
        __syncwarp();

        // O += P V — A-frags (a0,a2)/(a1,a3) as float2 (permuted P);
        // B-frags (b0,b1) as float2 from V^T (kpos permuted).
#pragma unroll
        for (int ks = 0; ks < 8; ks++) {
            const int k0 = ks * 8;
            float2 pa = *(const float2*)&QP[(rb + g) * AP + k0 + 2 * tig];
            float2 pb = *(const float2*)&QP[(rb + g + 8) * AP + k0 + 2 * tig];
            uint32_t a[4];
            a[0] = __float_as_uint(pa.x);
            a[1] = __float_as_uint(pb.x);
            a[2] = __float_as_uint(pa.y);
            a[3] = __float_as_uint(pb.y);
#pragma unroll
            for (int nt = 0; nt < 8; nt++) {
                float2 vv = *(const float2*)&Vc[(nt * 8 + g) * APK + k0 + 2 * tig];
                mma_tf32(o[nt], a, __float_as_uint(vv.x), __float_as_uint(vv.y));
            }
        }

        // Relative-V band (P read through the position map)
        if (near) {
#pragma unroll
            for (int dd = 0; dd < NW_; dd++) {
                int j0r = qi0 + dd - 4 - j0;
                if (j0r >= 0 && j0r < 64) {
                    float p = QP[(rb + g) * AP + (j0r & ~7) + posm(j0r)];
#pragma unroll
                    for (int nt = 0; nt < 8; nt++) {
                        int col = nt * 8 + 2 * tig;
                        o[nt][0] += p * Evs[dd * 64 + col];
                        o[nt][1] += p * Evs[dd * 64 + col + 1];
                    }
                }
                int j1r = qi1 + dd - 4 - j0;
                if (j1r >= 0 && j1r < 64) {
                    float p = QP[(rb + g + 8) * AP + (j1r & ~7) + posm(j1r)];
#pragma unroll
                    for (int nt = 0; nt < 8; nt++) {
                        int col = nt * 8 + 2 * tig;
                        o[nt][2] += p * Evs[dd * 64 + col];
                        o[nt][3] += p * Evs[dd * 64 + col + 1];
                    }
                }
            }
        }
        __syncthreads();   // all reads of buf cur done before re-prefetch
    }

    // Epilogue: normalize, tf32-round, store resT[b][l][h*64+dim].
    float inv0 = 1.0f / l0, inv1 = 1.0f / l1;
    float* r0p = g_resT + ((size_t)b * L_ + qi0) * C_ + h * D_;
    float* r1p = g_resT + ((size_t)b * L_ + qi1) * C_ + h * D_;
#pragma unroll
    for (int nt = 0; nt < 8; nt++) {
        int col = nt * 8 + 2 * tig;
        *(float2*)(r0p + col) = make_float2(__uint_as_float(f2tf32(o[nt][0] * inv0)),
                                            __uint_as_float(f2tf32(o[nt][1] * inv0)));
        *(float2*)(r1p + col) = make_float2(__uint_as_float(f2tf32(o[nt][2] * inv1)),
                                            __uint_as_float(f2tf32(o[nt][3] * inv1)));
    }
}

// ---------------------------------------------------------------------------
extern "C" void kernel_launch(void* const* d_in, const int* in_sizes, int n_in,
                              void* d_out, int out_size) {
    const float* x   = (const float*)d_in[0];
    const float* wq  = (const float*)d_in[1];
    const float* bq  = (const float*)d_in[2];
    const float* wk  = (const float*)d_in[3];
    const float* bk  = (const float*)d_in[4];
    const float* wv  = (const float*)d_in[5];
    const float* bv  = (const float*)d_in[6];
    const float* wo  = (const float*)d_in[7];
    const float* bo  = (const float*)d_in[8];
    const float* erk = (const float*)d_in[9];
    const float* erv = (const float*)d_in[10];
    float* out = (float*)d_out;

    float *gqT, *gkT, *gvCL, *gxT, *gresT, *gwr;
    cudaGetSymbolAddress((void**)&gqT,   g_qT);
    cudaGetSymbolAddress((void**)&gkT,   g_kT);
    cudaGetSymbolAddress((void**)&gvCL,  g_vCL);
    cudaGetSymbolAddress((void**)&gxT,   g_xT);
    cudaGetSymbolAddress((void**)&gresT, g_resT);
    cudaGetSymbolAddress((void**)&gwr,   g_wr);

    const int attn_smem = ATTN_SMEMF * 4;  // 115456 bytes -> 2 CTAs/SM
    const int gemm_smem = GEMM_SMEMF * 4;  // 73728 bytes
    cudaFuncSetAttribute(attn_mma, cudaFuncAttributeMaxDynamicSharedMemorySize,
                         attn_smem);
    cudaFuncSetAttribute(qkv_mma, cudaFuncAttributeMaxDynamicSharedMemorySize,
                         gemm_smem);
    cudaFuncSetAttribute(proj_mma, cudaFuncAttributeMaxDynamicSharedMemorySize,
                         gemm_smem);

    // x[b][c][l] -> tf32(xT[b][l][c]); round weights once
    dim3 tgrid(L_ / 32, C_ / 32, B_);
    transpose_kernel<<<tgrid, 256>>>(x, gxT, C_, L_);
    dim3 wgrid(C_ * C_ / 1024, 4);
    round_w<<<wgrid, 256>>>(wq, wk, wv, wo, gwr);

    // Fused QKV (q,k dim-permuted [b][l][c]; v l-permuted [b][c][l])
    dim3 qgrid(C_ / 128, L_ / 128, B_ * 3);   // (3, 8, 24)
    qkv_mma<<<qgrid, 256, gemm_smem>>>(bq, bk, bv, gxT, gqT, gkT, gvCL);

    // Tensor-core attention (128 q-rows per block, 2 CTAs/SM)
    dim3 agrid(L_ / 128, B_ * H_);            // (8, 48)
    attn_mma<<<agrid, 256, attn_smem>>>(erk, erv);

    // O projection
    dim3 ogrid(L_ / 128, C_ / 128, B_);       // (8, 3, 8)
    proj_mma<<<ogrid, 256, gemm_smem>>>(bo, gresT, out);
}

// round 16
// speedup vs baseline: 1.6497x; 1.0894x over previous
#include <cuda_runtime.h>
#include <cstdint>

#define B_ 8
#define C_ 384
#define L_ 1024
#define H_ 6
#define D_ 64
#define NW_ 9   // 2*window+1

// Scratch (allocation-free rule: device globals).
// g_qT: [b][l][c], dim-channels permuted within 8-groups (pos(c&7)).
// g_kT: [b][l][c], dim-channels permuted AND kpos rows (l) permuted.
// g_vCL: [b][c][l], kpos (l) permuted within 8-groups.
__device__ float g_qT[B_*L_*C_];
__device__ float g_kT[B_*L_*C_];
__device__ float g_vCL[B_*C_*L_];
__device__ float g_xT[B_*L_*C_];    // tf32-rounded
__device__ float g_resT[B_*L_*C_];  // tf32-rounded (attn epilogue)
__device__ float g_wr[4*C_*C_];     // tf32-rounded wq,wk,wv,wo

__device__ __forceinline__ uint32_t f2tf32(float f) {
    uint32_t r;
    asm("cvt.rna.tf32.f32 %0, %1;" : "=r"(r) : "f"(f));
    return r;
}

__device__ __forceinline__ void mma_tf32(float* d, const uint32_t* a,
                                         uint32_t b0, uint32_t b1) {
    asm volatile("mma.sync.aligned.m16n8k8.row.col.f32.tf32.tf32.f32 "
                 "{%0,%1,%2,%3}, {%4,%5,%6,%7}, {%8,%9}, {%0,%1,%2,%3};"
                 : "+f"(d[0]), "+f"(d[1]), "+f"(d[2]), "+f"(d[3])
                 : "r"(a[0]), "r"(a[1]), "r"(a[2]), "r"(a[3]),
                   "r"(b0), "r"(b1));
}

__device__ __forceinline__ uint32_t smem_u32(const void* p) {
    uint32_t a;
    asm("{ .reg .u64 t; cvta.to.shared.u64 t, %1; cvt.u32.u64 %0, t; }"
        : "=r"(a) : "l"(p));
    return a;
}
__device__ __forceinline__ void cp_async16(uint32_t s, const void* g) {
    asm volatile("cp.async.cg.shared.global [%0], [%1], 16;" :: "r"(s), "l"(g));
}
#define CP_COMMIT() asm volatile("cp.async.commit_group;" ::: "memory")
#define CP_WAIT1()  asm volatile("cp.async.wait_group 1;" ::: "memory")
#define CP_WAIT0()  asm volatile("cp.async.wait_group 0;" ::: "memory")

// position of element j within its 8-group after the permutation
__device__ __forceinline__ int posm(int j) { return ((j & 3) << 1) | ((j & 7) >> 2); }

// ===========================================================================
// Transpose + tf32 round: dst[b][col][row] = rna_tf32(src[b][row][col]).
// ===========================================================================
__global__ __launch_bounds__(256) void transpose_kernel(const float* __restrict__ src,
                                                        float* __restrict__ dst,
                                                        int rows, int cols) {
    __shared__ float tile[32][33];
    const int b = blockIdx.z;
    const int r0 = blockIdx.y * 32;
    const int c0 = blockIdx.x * 32;
    const int tx = threadIdx.x & 31, ty = threadIdx.x >> 5;
    const float* sb = src + (size_t)b * rows * cols;
    float* db = dst + (size_t)b * rows * cols;
#pragma unroll
    for (int i = 0; i < 4; i++)
        tile[ty + i * 8][tx] = sb[(size_t)(r0 + ty + i * 8) * cols + c0 + tx];
    __syncthreads();
#pragma unroll
    for (int i = 0; i < 4; i++)
        db[(size_t)(c0 + ty + i * 8) * rows + r0 + tx] =
            __uint_as_float(f2tf32(tile[tx][ty + i * 8]));
}

// ===========================================================================
// Round the four weight matrices to tf32 once.
// ===========================================================================
__global__ __launch_bounds__(256) void round_w(const float* __restrict__ w0,
                                               const float* __restrict__ w1,
                                               const float* __restrict__ w2,
                                               const float* __restrict__ w3,
                                               float* __restrict__ dst) {
    const int m = blockIdx.y;
    const float* src = (m == 0) ? w0 : (m == 1) ? w1 : (m == 2) ? w2 : w3;
    int idx = (blockIdx.x * 256 + threadIdx.x) * 4;
    float4 v = *(const float4*)(src + idx);
    uint4 t = make_uint4(f2tf32(v.x), f2tf32(v.y), f2tf32(v.z), f2tf32(v.w));
    *(uint4*)(dst + (size_t)m * C_ * C_ + idx) = t;
}

// ===========================================================================
// cp.async double-buffered tf32 GEMM core (R12-proven).
// ===========================================================================
#define GEMM_SMEMF (4 * 128 * 36)   // 73728 bytes

__device__ __forceinline__ void gemm_stage(uint32_t sa, uint32_t sb,
                                           const float* Ag, const float* Bg,
                                           int c0, int tid) {
    const int r_ = tid >> 3;
    const int u  = (tid & 7) * 4;
#pragma unroll
    for (int it = 0; it < 4; it++) {
        int row = it * 32 + r_;
        uint32_t so = (uint32_t)(row * 36 + u) * 4;
        cp_async16(sa + so, Ag + (size_t)row * C_ + c0 + u);
        cp_async16(sb + so, Bg + (size_t)row * C_ + c0 + u);
    }
}

__device__ __forceinline__ void gemm_core(float acc[2][8][4], float* smem,
                                          const float* Ag, const float* Bg,
                                          int tid) {
    const int lane = tid & 31;
    const int g = lane >> 2, tig = lane & 3;
    const int wid = tid >> 5;
    const int warpM = wid & 3, warpN = wid >> 2;
    float* As = smem;
    float* Bs = smem + 2 * 128 * 36;
    const uint32_t as_u = smem_u32(As);
    const uint32_t bs_u = smem_u32(Bs);
    const uint32_t bufb = 128 * 36 * 4;

    gemm_stage(as_u, bs_u, Ag, Bg, 0, tid);
    CP_COMMIT();

    for (int ct = 0; ct < C_ / 32; ct++) {
        const int cur = ct & 1;
        if (ct + 1 < C_ / 32) {
            gemm_stage(as_u + (cur ^ 1) * bufb, bs_u + (cur ^ 1) * bufb,
                       Ag, Bg, (ct + 1) * 32, tid);
            CP_COMMIT();
            CP_WAIT1();
        } else {
            CP_WAIT0();
        }
        __syncthreads();
        const float* Ac = As + cur * 128 * 36;
        const float* Bc = Bs + cur * 128 * 36;
#pragma unroll
        for (int ks = 0; ks < 4; ks++) {
            const int k0 = ks * 8;
            uint32_t a[2][4];
#pragma unroll
            for (int mt = 0; mt < 2; mt++) {
                int rb = warpM * 32 + mt * 16;
                a[mt][0] = __float_as_uint(Ac[(rb + g) * 36 + k0 + tig]);
                a[mt][1] = __float_as_uint(Ac[(rb + g + 8) * 36 + k0 + tig]);
                a[mt][2] = __float_as_uint(Ac[(rb + g) * 36 + k0 + tig + 4]);
                a[mt][3] = __float_as_uint(Ac[(rb + g + 8) * 36 + k0 + tig + 4]);
            }
#pragma unroll
            for (int nt = 0; nt < 8; nt++) {
                int nb = warpN * 64 + nt * 8;
                uint32_t b0 = __float_as_uint(Bc[(nb + g) * 36 + k0 + tig]);
                uint32_t b1 = __float_as_uint(Bc[(nb + g) * 36 + k0 + tig + 4]);
#pragma unroll
                for (int mt = 0; mt < 2; mt++)
                    mma_tf32(acc[mt][nt], a[mt], b0, b1);
            }
        }
        __syncthreads();
    }
}

// ===========================================================================
// Fused QKV projection.
//  q: [b][l][c] dim-permuted.
//  k: [b][l][c] dim-permuted + kpos-row permuted.
//  v: [b][c][l] l(kpos)-permuted.
// ===========================================================================
__global__ __launch_bounds__(256) void qkv_mma(const float* __restrict__ bq,
                                               const float* __restrict__ bk,
                                               const float* __restrict__ bv,
                                               const float* __restrict__ XT,
                                               float* __restrict__ q,
                                               float* __restrict__ k,
                                               float* __restrict__ v) {
    extern __shared__ float smem[];
    const int tid = threadIdx.x;
    const int lane = tid & 31;
    const int g = lane >> 2, tig = lane & 3;
    const int wid = tid >> 5;
    const int warpM = wid & 3, warpN = wid >> 2;
    const int pid = blockIdx.z % 3;
    const int b   = blockIdx.z / 3;
    const int l0  = blockIdx.y * 128;
    const int o0  = blockIdx.x * 128;

    const float* bias = (pid == 0) ? bq : (pid == 1) ? bk : bv;
    float* Y          = (pid == 0) ? q  : (pid == 1) ? k  : v;
    const float* Ag = XT + ((size_t)b * L_ + l0) * C_;
    const float* Bg = g_wr + (size_t)pid * C_ * C_ + (size_t)o0 * C_;

    float acc[2][8][4];
#pragma unroll
    for (int mt = 0; mt < 2; mt++)
#pragma unroll
        for (int nt = 0; nt < 8; nt++)
#pragma unroll
            for (int i = 0; i < 4; i++) acc[mt][nt][i] = 0.f;

    gemm_core(acc, smem, Ag, Bg, tid);

    const int b0g = 2 * tig, b1g = 2 * tig + 1;
    const int p0 = posm(b0g), p1 = posm(b1g);
    const int pg = posm(g);   // kpos-row permutation (k and v)

#pragma unroll
    for (int mt = 0; mt < 2; mt++) {
        int lr0 = l0 + warpM * 32 + mt * 16;
#pragma unroll
        for (int nt = 0; nt < 8; nt++) {
            int grp = o0 + warpN * 64 + nt * 8;
            float bv0 = bias[grp + b0g], bv1 = bias[grp + b1g];
            float v0 = __uint_as_float(f2tf32(acc[mt][nt][0] + bv0));
            float v1 = __uint_as_float(f2tf32(acc[mt][nt][1] + bv1));
            float v2 = __uint_as_float(f2tf32(acc[mt][nt][2] + bv0));
            float v3 = __uint_as_float(f2tf32(acc[mt][nt][3] + bv1));
            if (pid == 0) {        // q: rows unpermuted, dims permuted
                float* y0 = Y + ((size_t)b * L_ + lr0 + g) * C_;
                float* y1 = Y + ((size_t)b * L_ + lr0 + g + 8) * C_;
                y0[grp + p0] = v0;  y0[grp + p1] = v1;
                y1[grp + p0] = v2;  y1[grp + p1] = v3;
            } else if (pid == 1) { // k: rows (kpos) permuted, dims permuted
                float* y0 = Y + ((size_t)b * L_ + lr0 + pg) * C_;
                float* y1 = Y + ((size_t)b * L_ + lr0 + 8 + pg) * C_;
                y0[grp + p0] = v0;  y0[grp + p1] = v1;
                y1[grp + p0] = v2;  y1[grp + p1] = v3;
            } else {               // v: [b][c][l], l permuted
                float* ya = Y + ((size_t)b * C_ + grp + b0g) * L_;
                float* yb = Y + ((size_t)b * C_ + grp + b1g) * L_;
                ya[lr0 + pg] = v0;      yb[lr0 + pg] = v1;
                ya[lr0 + 8 + pg] = v2;  yb[lr0 + 8 + pg] = v3;
            }
        }
    }
}

// ===========================================================================
// O projection: out[b][o][l] = sum_c W[o][c] * resT[b][l][c] + bias[o]
// ===========================================================================
__global__ __launch_bounds__(256) void proj_mma(const float* __restrict__ bias,
                                                const float* __restrict__ XT,
                                                float* __restrict__ Y) {
    extern __shared__ float smem[];
    const int tid = threadIdx.x;
    const int lane = tid & 31;
    const int g = lane >> 2, tig = lane & 3;
    const int wid = tid >> 5;
    const int warpM = wid & 3, warpN = wid >> 2;
    const int b  = blockIdx.z;
    const int o0 = blockIdx.y * 128;
    const int l0 = blockIdx.x * 128;

    const float* Ag = g_wr + (size_t)3 * C_ * C_ + (size_t)o0 * C_;
    const float* Bg = XT + ((size_t)b * L_ + l0) * C_;

    float acc[2][8][4];
#pragma unroll
    for (int mt = 0; mt < 2; mt++)
#pragma unroll
        for (int nt = 0; nt < 8; nt++)
#pragma unroll
            for (int i = 0; i < 4; i++) acc[mt][nt][i] = 0.f;

    gemm_core(acc, smem, Ag, Bg, tid);

#pragma unroll
    for (int mt = 0; mt < 2; mt++) {
        int r0 = o0 + warpM * 32 + mt * 16;
        float bv0 = bias[r0 + g];
        float bv1 = bias[r0 + g + 8];
        float* y0 = Y + ((size_t)b * C_ + r0 + g) * L_;
        float* y1 = Y + ((size_t)b * C_ + r0 + g + 8) * L_;
#pragma unroll
        for (int nt = 0; nt < 8; nt++) {
            int col = l0 + warpN * 64 + nt * 8 + 2 * tig;
            *(float2*)(y0 + col) = make_float2(acc[mt][nt][0] + bv0, acc[mt][nt][1] + bv0);
            *(float2*)(y1 + col) = make_float2(acc[mt][nt][2] + bv1, acc[mt][nt][3] + bv1);
        }
    }
}

// ===========================================================================
// Tensor-core flash attention. K kpos-permuted => QK D-frag columns align
// with PV A-frag slots: PV consumes f2tf32(s[ks][.]) from REGISTERS.
// P goes to smem only in near-diagonal tiles (band-V cross-lane reads).
// S slot semantics: s[nt][0]=col nt*8+tig, s[nt][1]=col nt*8+tig+4 (rows g),
// s[nt][2],s[nt][3] same cols (rows g+8).
// ===========================================================================
#define AP  68                   // QP stride
#define APK 72                   // K & V smem stride
#define KVF 4608                 // floats per 64x72 buffer
#define SM_QP  0                 // Q-stage then P(near tiles): [128][68]
#define SM_K   8704              // 2 x [64][72]
#define SM_V   17920             // 2 x [64][72]
#define SM_EV  27136             // [9][64]
#define SM_QEK 27712             // [128][9]
#define ATTN_SMEMF 28864         // 115456 bytes
// Eks overlaps V buffer 1 (prologue-only; protected by pre-mainloop sync)

__global__ __launch_bounds__(256, 2) void attn_mma(const float* __restrict__ erk,
                                                   const float* __restrict__ erv) {
    extern __shared__ float sm[];
    float* QP  = sm + SM_QP;
    float* Ks  = sm + SM_K;
    float* Vs  = sm + SM_V;
    float* Evs = sm + SM_EV;
    float* qEk = sm + SM_QEK;
    float* Eks = Vs + KVF;       // overlaps V buffer 1 during prologue

    const int tid = threadIdx.x;
    const int w = tid >> 5, lane = tid & 31;
    const int g = lane >> 2, tig = lane & 3;
    const int rb = w * 16;
    const int i0 = blockIdx.x * 128;
    const int bh = blockIdx.y;
    const int b = bh / H_, h = bh % H_;

    const float* QT = g_qT + (size_t)b * L_ * C_ + h * D_;
    const float* KT = g_kT + (size_t)b * L_ * C_ + h * D_;
    const float* VC = g_vCL + ((size_t)b * C_ + h * D_) * L_;

    const uint32_t ks_u = smem_u32(Ks);
    const uint32_t vs_u = smem_u32(Vs);
    const int cp_r  = tid >> 4;          // 0..15
    const int cp_d4 = (tid & 15) * 4;

    // Prefetch K/V tile 0 into buffer 0 (both arrays pre-permuted in global).
#pragma unroll
    for (int it = 0; it < 4; it++) {
        int r = it * 16 + cp_r;
        cp_async16(ks_u + (uint32_t)(r * APK + cp_d4) * 4, KT + (size_t)r * C_ + cp_d4);
        cp_async16(vs_u + (uint32_t)(r * APK + cp_d4) * 4, VC + (size_t)r * L_ + cp_d4);
    }
    CP_COMMIT();

    // Stage Q (pre-scaled by 1/8, exact; dim-permuted in global).
#pragma unroll
    for (int it = 0; it < 8; it++) {
        int idx = it * 256 + tid;
        int r = idx >> 4, d4 = (idx & 15) * 4;
        float4 q4 = *(const float4*)(QT + (size_t)(i0 + r) * C_ + d4);
        QP[r * AP + d4 + 0] = q4.x * 0.125f;
        QP[r * AP + d4 + 1] = q4.y * 0.125f;
        QP[r * AP + d4 + 2] = q4.z * 0.125f;
        QP[r * AP + d4 + 3] = q4.w * 0.125f;
    }
    for (int e = tid; e < NW_ * 64; e += 256) {
        int dd = e >> 6, r = e & 63;
        Eks[dd * 64 + r] = erk[(h * NW_ + dd) * 64 + r];
        Evs[dd * 64 + r] = erv[(h * NW_ + dd) * 64 + r];
    }
    __syncthreads();

    // qEk[i][dd] = (q_i/8) . Ek[dd]; GLOBAL d order through the permutation.
    for (int e = tid; e < 128 * NW_; e += 256) {
        int dd = e / 128, i = e % 128;
        float s = 0.f;
#pragma unroll
        for (int d = 0; d < 64; d++) {
            int pos = (d & ~7) | posm(d);
            s += QP[i * AP + pos] * Eks[dd * 64 + d];
        }
        qEk[i * NW_ + dd] = s;
    }

    // Q fragments: permuted layout => (k=tig, k=tig+4) adjacent float2.
    uint32_t qf[8][4];
#pragma unroll
    for (int ks = 0; ks < 8; ks++) {
        const int k0 = ks * 8;
        float2 qa = *(const float2*)&QP[(rb + g) * AP + k0 + 2 * tig];
        float2 qb = *(const float2*)&QP[(rb + g + 8) * AP + k0 + 2 * tig];
        qf[ks][0] = __float_as_uint(qa.x);
        qf[ks][1] = __float_as_uint(qb.x);
        qf[ks][2] = __float_as_uint(qa.y);
        qf[ks][3] = __float_as_uint(qb.y);
    }
    __syncthreads();   // Eks reads done before V-buf1 prefetch (jt=0);
                       // Q reads done before P staging overwrites QP.

    float m0 = -1e30f, m1 = -1e30f, l0 = 0.f, l1 = 0.f;
    float o[8][4];
#pragma unroll
    for (int nt = 0; nt < 8; nt++)
#pragma unroll
        for (int i = 0; i < 4; i++) o[nt][i] = 0.f;

    const int qi0 = i0 + rb + g;
    const int qi1 = qi0 + 8;
    const int NT = L_ / 64;

    for (int jt = 0; jt < NT; jt++) {
        const int j0 = jt * 64;
        const int cur = jt & 1;
        if (jt + 1 < NT) {
            const float* Kn = KT + (size_t)(j0 + 64) * C_;
            const float* Vn = VC + (size_t)(j0 + 64);
#pragma unroll
            for (int it = 0; it < 4; it++) {
                int r = it * 16 + cp_r;
                cp_async16(ks_u + (uint32_t)((cur ^ 1) * KVF + r * APK + cp_d4) * 4,
                           Kn + (size_t)r * C_ + cp_d4);
                cp_async16(vs_u + (uint32_t)((cur ^ 1) * KVF + r * APK + cp_d4) * 4,
                           Vn + (size_t)r * L_ + cp_d4);
            }
            CP_COMMIT();
            CP_WAIT1();
        } else {
            CP_WAIT0();
        }
        __syncthreads();

        const float* Kc = Ks + cur * KVF;
        const float* Vc = Vs + cur * KVF;

        // S = (Q/8) K^T — K fragment (b0,b1) as one float2.
        // Column semantics permuted: s[nt][0]~col nt*8+tig, s[nt][1]~+tig+4.
        float s[8][4];
#pragma unroll
        for (int nt = 0; nt < 8; nt++)
#pragma unroll
            for (int i = 0; i < 4; i++) s[nt][i] = 0.f;
#pragma unroll
        for (int ks = 0; ks < 8; ks++) {
            const int k0 = ks * 8;
#pragma unroll
            for (int nt = 0; nt < 8; nt++) {
                float2 kk = *(const float2*)&Kc[(nt * 8 + g) * APK + k0 + 2 * tig];
                mma_tf32(s[nt], qf[ks], __float_as_uint(kk.x), __float_as_uint(kk.y));
            }
        }

        // Relative-K band bias (new column semantics)
        const bool near = (j0 + 63 >= i0 - 4) && (j0 <= i0 + 131);
        if (near) {
#pragma unroll
            for (int nt = 0; nt < 8; nt++) {
                int jA = j0 + nt * 8 + tig;       // slots 0,2
                int jB = jA + 4;                  // slots 1,3
                int d;
                d = jA - qi0; if (d >= -4 && d <= 4) s[nt][0] += qEk[(rb + g) * NW_ + d + 4];
                d = jB - qi0; if (d >= -4 && d <= 4) s[nt][1] += qEk[(rb + g) * NW_ + d + 4];
                d = jA - qi1; if (d >= -4 && d <= 4) s[nt][2] += qEk[(rb + g + 8) * NW_ + d + 4];
                d = jB - qi1; if (d >= -4 && d <= 4) s[nt][3] += qEk[(rb + g + 8) * NW_ + d + 4];
            }
        }

        // Online softmax (4-lane row reductions; sum order permuted — OK)
        float tm0 = -1e30f, tm1 = -1e30f;
#pragma unroll
        for (int nt = 0; nt < 8; nt++) {
            tm0 = fmaxf(tm0, fmaxf(s[nt][0], s[nt][1]));
            tm1 = fmaxf(tm1, fmaxf(s[nt][2], s[nt][3]));
        }
#pragma unroll
        for (int off = 1; off <= 2; off <<= 1) {
            tm0 = fmaxf(tm0, __shfl_xor_sync(0xffffffffu, tm0, off));
            tm1 = fmaxf(tm1, __shfl_xor_sync(0xffffffffu, tm1, off));
        }
        float mn0 = fmaxf(m0, tm0), mn1 = fmaxf(m1, tm1);
        float ts0 = 0.f, ts1 = 0.f;
#pragma unroll
        for (int nt = 0; nt < 8; nt++) {
            s[nt][0] = __expf(s[nt][0] - mn0);
            s[nt][1] = __expf(s[nt][1] - mn0);
            s[nt][2] = __expf(s[nt][2] - mn1);
            s[nt][3] = __expf(s[nt][3] - mn1);
            ts0 += s[nt][0] + s[nt][1];
            ts1 += s[nt][2] + s[nt][3];
        }
#pragma unroll
        for (int off = 1; off <= 2; off <<= 1) {
            ts0 += __shfl_xor_sync(0xffffffffu, ts0, off);
            ts1 += __shfl_xor_sync(0xffffffffu, ts1, off);
        }
        float al0 = __expf(m0 - mn0), al1 = __expf(m1 - mn1);
        l0 = l0 * al0 + ts0;  m0 = mn0;
        l1 = l1 * al1 + ts1;  m1 = mn1;
#pragma unroll
        for (int nt = 0; nt < 8; nt++) {
            o[nt][0] *= al0; o[nt][1] *= al0;
            o[nt][2] *= al1; o[nt][3] *= al1;
        }

        // Near tiles only: stage P at GLOBAL column positions for band-V.
        if (near) {
#pragma unroll
            for (int nt = 0; nt < 8; nt++) {
                int cA = nt * 8 + tig, cB = cA + 4;
                QP[(rb + g) * AP + cA]     = __uint_as_float(f2tf32(s[nt][0]));
                QP[(rb + g) * AP + cB]     = __uint_as_float(f2tf32(s[nt][1]));
                QP[(rb + g + 8) * AP + cA] = __uint_as_float(f2tf32(s[nt][2]));
                QP[(rb + g + 8) * AP + cB] = __uint_as_float(f2tf32(s[nt][3]));
            }
            __syncwarp();
        }

        // O += P V — A-frags straight from registers (D-frag aligns with
        // A-frag thanks to K's kpos permutation); B-frags float2 from V^T.
#pragma unroll
        for (int ks = 0; ks < 8; ks++) {
            const int k0 = ks * 8;
            uint32_t a[4];
            a[0] = f2tf32(s[ks][0]);
            a[1] = f2tf32(s[ks][2]);
            a[2] = f2tf32(s[ks][1]);
            a[3] = f2tf32(s[ks][3]);
#pragma unroll
            for (int nt = 0; nt < 8; nt++) {
                float2 vv = *(const float2*)&Vc[(nt * 8 + g) * APK + k0 + 2 * tig];
                mma_tf32(o[nt], a, __float_as_uint(vv.x), __float_as_uint(vv.y));
            }
        }

        // Relative-V band (P at global columns in QP)
        if (near) {
#pragma unroll
            for (int dd = 0; dd < NW_; dd++) {
                int j0r = qi0 + dd - 4 - j0;
                if (j0r >= 0 && j0r < 64) {
                    float p = QP[(rb + g) * AP + j0r];
#pragma unroll
                    for (int nt = 0; nt < 8; nt++) {
                        int col = nt * 8 + 2 * tig;
                        o[nt][0] += p * Evs[dd * 64 + col];
                        o[nt][1] += p * Evs[dd * 64 + col + 1];
                    }
                }
                int j1r = qi1 + dd - 4 - j0;
                if (j1r >= 0 && j1r < 64) {
                    float p = QP[(rb + g + 8) * AP + j1r];
#pragma unroll
                    for (int nt = 0; nt < 8; nt++) {
                        int col = nt * 8 + 2 * tig;
                        o[nt][2] += p * Evs[dd * 64 + col];
                        o[nt][3] += p * Evs[dd * 64 + col + 1];
                    }
                }
            }
        }
        __syncthreads();   // all reads of buf cur done before re-prefetch
    }

    // Epilogue: normalize, tf32-round, store resT[b][l][h*64+dim].
    float inv0 = 1.0f / l0, inv1 = 1.0f / l1;
    float* r0p = g_resT + ((size_t)b * L_ + qi0) * C_ + h * D_;
    float* r1p = g_resT + ((size_t)b * L_ + qi1) * C_ + h * D_;
#pragma unroll
    for (int nt = 0; nt < 8; nt++) {
        int col = nt * 8 + 2 * tig;
        *(float2*)(r0p + col) = make_float2(__uint_as_float(f2tf32(o[nt][0] * inv0)),
                                            __uint_as_float(f2tf32(o[nt][1] * inv0)));
        *(float2*)(r1p + col) = make_float2(__uint_as_float(f2tf32(o[nt][2] * inv1)),
                                            __uint_as_float(f2tf32(o[nt][3] * inv1)));
    }
}

// ---------------------------------------------------------------------------
extern "C" void kernel_launch(void* const* d_in, const int* in_sizes, int n_in,
                              void* d_out, int out_size) {
    const float* x   = (const float*)d_in[0];
    const float* wq  = (const float*)d_in[1];
    const float* bq  = (const float*)d_in[2];
    const float* wk  = (const float*)d_in[3];
    const float* bk  = (const float*)d_in[4];
    const float* wv  = (const float*)d_in[5];
    const float* bv  = (const float*)d_in[6];
    const float* wo  = (const float*)d_in[7];
    const float* bo  = (const float*)d_in[8];
    const float* erk = (const float*)d_in[9];
    const float* erv = (const float*)d_in[10];
    float* out = (float*)d_out;

    float *gqT, *gkT, *gvCL, *gxT, *gresT, *gwr;
    cudaGetSymbolAddress((void**)&gqT,   g_qT);
    cudaGetSymbolAddress((void**)&gkT,   g_kT);
    cudaGetSymbolAddress((void**)&gvCL,  g_vCL);
    cudaGetSymbolAddress((void**)&gxT,   g_xT);
    cudaGetSymbolAddress((void**)&gresT, g_resT);
    cudaGetSymbolAddress((void**)&gwr,   g_wr);

    const int attn_smem = ATTN_SMEMF * 4;  // 115456 bytes -> 2 CTAs/SM
    const int gemm_smem = GEMM_SMEMF * 4;  // 73728 bytes
    cudaFuncSetAttribute(attn_mma, cudaFuncAttributeMaxDynamicSharedMemorySize,
                         attn_smem);
    cudaFuncSetAttribute(qkv_mma, cudaFuncAttributeMaxDynamicSharedMemorySize,
                         gemm_smem);
    cudaFuncSetAttribute(proj_mma, cudaFuncAttributeMaxDynamicSharedMemorySize,
                         gemm_smem);

    // x[b][c][l] -> tf32(xT[b][l][c]); round weights once
    dim3 tgrid(L_ / 32, C_ / 32, B_);
    transpose_kernel<<<tgrid, 256>>>(x, gxT, C_, L_);
    dim3 wgrid(C_ * C_ / 1024, 4);
    round_w<<<wgrid, 256>>>(wq, wk, wv, wo, gwr);

    // Fused QKV (q dim-perm; k dim+kpos-perm; v kpos-perm channel-major)
    dim3 qgrid(C_ / 128, L_ / 128, B_ * 3);   // (3, 8, 24)
    qkv_mma<<<qgrid, 256, gemm_smem>>>(bq, bk, bv, gxT, gqT, gkT, gvCL);

    // Tensor-core attention (128 q-rows per block, 2 CTAs/SM)
    dim3 agrid(L_ / 128, B_ * H_);            // (8, 48)
    attn_mma<<<agrid, 256, attn_smem>>>(erk, erv);

    // O projection
    dim3 ogrid(L_ / 128, C_ / 128, B_);       // (8, 3, 8)
    proj_mma<<<ogrid, 256, gemm_smem>>>(bo, gresT, out);
}